// round 9
// baseline (speedup 1.0000x reference)
#include <cuda_runtime.h>
#include <cstdint>
#include <cstddef>

// ---------------------------------------------------------------------------
// Problem constants
// ---------------------------------------------------------------------------
#define BB    32
#define CIN   128
#define COUT  256
#define HH    32
#define WW    32
#define HWP   1024              // H*W
#define MROWS 32768             // B*H*W
#define MEMN  64
#define EPSBN 1e-5f

// ---------------------------------------------------------------------------
// Scratch (single __device__ array; no allocations anywhere)
// ---------------------------------------------------------------------------
#define OFF_XN     0ull                      // 32768*128
#define OFF_T1     4194304ull                // 32768*256
#define OFF_T2     12582912ull
#define OFF_XF     20971520ull
#define OFF_RETR   29360128ull
#define OFF_T1B    37748736ull               // bn1+relu(t1), rounded
#define OFF_SCV    46137344ull
#define OFF_L      54525952ull               // 32768*64
#define OFF_W1R    56623104ull               // 256*1152
#define OFF_W2R    56918016ull               // 256*2304
#define OFF_W3R    57507840ull               // 256*256  (ctrl_w1 rounded)
#define OFF_WGR    57573376ull               // 256*512  (gate_w rounded)
#define OFF_WSCR   57704448ull               // 256*128  (sc_w rounded)
#define OFF_KW     57737216ull               // 64*256   (keys @ ctrl_w2, rounded)
#define OFF_KB     57753600ull               // 64 (padded 256)
#define OFF_PSUM   57753856ull               // 256*256
#define OFF_PSQ    57819392ull
#define OFF_PAVG   57884928ull
#define OFF_PMAX   57950464ull
#define OFF_CATT   58016000ull               // 32*256
#define OFF_SPM    58024192ull               // 32768
#define OFF_SPX    58056960ull
#define OFF_SA     58089728ull
#define OFF_BN1SC  58122496ull               // 256 each
#define OFF_BN1SH  58122752ull
#define OFF_BN2SC  58123008ull
#define OFF_BN2SH  58123264ull
#define OFF_SCSC   58123520ull
#define OFF_SCSH   58123776ull
#define SCRATCH_TOTAL 58124032ull

__device__ float g_scratch[SCRATCH_TOTAL];

// ---------------------------------------------------------------------------
// tf32 helpers (plain sm_80+ PTX — compiles for sm_103 non-"a" target)
// ---------------------------------------------------------------------------
__device__ __forceinline__ uint32_t f2tf32(float x) {
    uint32_t r;
    asm("cvt.rna.tf32.f32 %0, %1;" : "=r"(r) : "f"(x));
    return r;
}
__device__ __forceinline__ float tf32f(float x) {
    return __uint_as_float(f2tf32(x));
}
__device__ __forceinline__ void mma_tf32(float* d, const uint32_t* a, const uint32_t* b) {
    asm volatile(
        "mma.sync.aligned.m16n8k8.row.col.f32.tf32.tf32.f32 "
        "{%0,%1,%2,%3}, {%4,%5,%6,%7}, {%8,%9}, {%0,%1,%2,%3};"
        : "+f"(d[0]), "+f"(d[1]), "+f"(d[2]), "+f"(d[3])
        : "r"(a[0]), "r"(a[1]), "r"(a[2]), "r"(a[3]), "r"(b[0]), "r"(b[1]));
}

// ---------------------------------------------------------------------------
// tf32 tensor-core GEMM (mma.sync), 512 threads, 4x4 warp grid, 32x32 warp tile
//   C[M,N] = alpha * A[M,K] * Wt[N,K]^T  (+bias)(relu|sigmoid)(tf32)(final)
// BM=128 (grid.x = M/128), BN template (grid.y = N/BN), BK=32.
// All A/B operands are tf32-pre-rounded floats. Modes:
//   c4shift==0 : plain A (K-concat via Ksplit / A2)
//   c4shift>0  : implicit im2col 3x3 pad1 over NHWC src with C=1<<c4shift
// F_FINAL (gate GEMM only, BN=128): epilogue computes
//   mo=g*retr+(1-g)*xf; spike=(0.1*mo>=1); out=relu(spike + scv*scsc+scsh)
//   and writes NCHW-transposed directly to outp. No C store.
// ---------------------------------------------------------------------------
#define F_BIAS  1
#define F_RELU  2
#define F_SIG   8
#define F_TF32  16
#define F_FINAL 32

template<int BN>
__global__ void __launch_bounds__(512, 2)
k_mma(const float* __restrict__ A, const float* __restrict__ A2, int Ksplit,
      int lda, int lda2, int c4shift,
      const float* __restrict__ Wt, int ldw,
      float* __restrict__ Cc, const float* __restrict__ bias,
      int N, int K, float alpha, int flags,
      const float* __restrict__ retr, const float* __restrict__ xfp,
      const float* __restrict__ scvp,
      const float* __restrict__ scscp, const float* __restrict__ scshp,
      float* __restrict__ outp)
{
    constexpr int NB4  = BN / 64;            // B float4 loads per thread
    constexpr int NTW  = BN / 32;            // n-tiles (8 cols) per warp
    constexpr int ASZ  = 32 * 132;           // A stage floats
    constexpr int BSZ  = (BN / 8) * 4 * 66;  // B stage floats
    constexpr int STG  = ASZ + BSZ;

    extern __shared__ __align__(16) uint32_t dsm[];

    const int tid  = threadIdx.x;
    const int lane = tid & 31;
    const int wid  = tid >> 5;
    const int wm   = wid & 3;
    const int wn   = wid >> 2;
    const int bm   = blockIdx.x * 128;
    const int bn   = blockIdx.y * BN;

    float acc[2][NTW][4];
#pragma unroll
    for (int i = 0; i < 2; i++)
#pragma unroll
        for (int j = 0; j < NTW; j++)
#pragma unroll
            for (int q = 0; q < 4; q++) acc[i][j][q] = 0.f;

    uint32_t Areg[2][4];
    uint32_t Breg[NB4][4];

    auto loadA = [&](int k0) {
#pragma unroll
        for (int t = 0; t < 2; t++) {
            int idx = tid + t * 512;
            int r = idx >> 3, c4 = idx & 7;
            int kg = k0 + (c4 << 2);
            float4 v = make_float4(0.f, 0.f, 0.f, 0.f);
            if (c4shift) {
                int tap = kg >> c4shift;
                int ic  = kg & ((1 << c4shift) - 1);
                int t3  = tap / 3;
                int m   = bm + r;
                int yy  = ((m >> 5) & 31) + t3 - 1;
                int xx  = (m & 31) + (tap - t3 * 3) - 1;
                if ((unsigned)yy < 32u && (unsigned)xx < 32u)
                    v = *(const float4*)(A +
                        (((size_t)((m >> 10) << 10) + (yy << 5) + xx) << c4shift) + ic);
            } else {
                const float* p;
                if (kg < Ksplit) p = A  + (size_t)(bm + r) * lda  + kg;
                else             p = A2 + (size_t)(bm + r) * lda2 + (kg - Ksplit);
                v = *(const float4*)p;
            }
            Areg[t][0] = __float_as_uint(v.x); Areg[t][1] = __float_as_uint(v.y);
            Areg[t][2] = __float_as_uint(v.z); Areg[t][3] = __float_as_uint(v.w);
        }
    };

    auto loadB = [&](int k0) {
#pragma unroll
        for (int t = 0; t < NB4; t++) {
            int idx = tid + t * 512;
            int r = idx >> 3, c4 = idx & 7;
            float4 v = *(const float4*)(Wt + (size_t)(bn + r) * ldw + k0 + (c4 << 2));
            Breg[t][0] = __float_as_uint(v.x); Breg[t][1] = __float_as_uint(v.y);
            Breg[t][2] = __float_as_uint(v.z); Breg[t][3] = __float_as_uint(v.w);
        }
    };

    auto stsA = [&](int st) {
        uint32_t* sA = dsm + st * STG;
#pragma unroll
        for (int t = 0; t < 2; t++) {
            int idx = tid + t * 512;
            int r = idx >> 3, c4 = idx & 7;
            int mt = r >> 4, rp = r & 15, kt = c4 >> 1;
            uint32_t* tp = sA + (mt * 4 + kt) * 132;
            int base = ((rp & 7) << 4) + (rp >> 3) + ((c4 & 1) << 1);
            tp[base + 0]  = Areg[t][0];
            tp[base + 4]  = Areg[t][1];
            tp[base + 8]  = Areg[t][2];
            tp[base + 12] = Areg[t][3];
        }
    };

    auto stsB = [&](int st) {
        uint32_t* sB = dsm + st * STG + ASZ;
#pragma unroll
        for (int t = 0; t < NB4; t++) {
            int idx = tid + t * 512;
            int r = idx >> 3, c4 = idx & 7;
            int nt = r >> 3, np = r & 7, kt = c4 >> 1;
            uint32_t* tp = sB + (nt * 4 + kt) * 66;
            int base = (np << 3) + (c4 & 1);
            tp[base + 0] = Breg[t][0];
            tp[base + 2] = Breg[t][1];
            tp[base + 4] = Breg[t][2];
            tp[base + 6] = Breg[t][3];
        }
    };

    auto compute = [&](int st) {
        const uint32_t* sA = dsm + st * STG;
        const uint32_t* sB = sA + ASZ;
#pragma unroll
        for (int kt = 0; kt < 4; kt++) {
            uint32_t af[2][4];
#pragma unroll
            for (int mt2 = 0; mt2 < 2; mt2++)
                *(uint4*)af[mt2] =
                    *(const uint4*)(sA + ((wm * 2 + mt2) * 4 + kt) * 132 + lane * 4);
            uint32_t bf[NTW][2];
#pragma unroll
            for (int nt2 = 0; nt2 < NTW; nt2++)
                *(uint2*)bf[nt2] =
                    *(const uint2*)(sB + ((wn * NTW + nt2) * 4 + kt) * 66 + lane * 2);
#pragma unroll
            for (int mt2 = 0; mt2 < 2; mt2++)
#pragma unroll
                for (int nt2 = 0; nt2 < NTW; nt2++)
                    mma_tf32(acc[mt2][nt2], af[mt2], bf[nt2]);
        }
    };

    const int nIter = K >> 5;
    loadA(0); loadB(0);
    stsA(0);  stsB(0);
    if (nIter > 1) { loadA(32); loadB(32); }
    __syncthreads();
    for (int it = 0; it < nIter; ++it) {
        if (it + 1 < nIter) { stsA((it + 1) & 1); stsB((it + 1) & 1); }
        if (it + 2 < nIter) { loadA((it + 2) << 5); loadB((it + 2) << 5); }
        compute(it & 1);
        __syncthreads();
    }

    const int g = lane >> 2, t4 = lane & 3;

    if (flags & F_FINAL) {
        // fused gate->final epilogue (BN==128 path only)
        float* T = (float*)dsm;   // 128 x 128 tile, stride 129 (mainloop done)
#pragma unroll
        for (int mt2 = 0; mt2 < 2; mt2++) {
#pragma unroll
            for (int nt2 = 0; nt2 < NTW; nt2++) {
                int cl = wn * (NTW * 8) + nt2 * 8 + t4 * 2;
                int col = bn + cl;
                float2 bv = *(const float2*)(bias + col);
                float2 ssc = *(const float2*)(scscp + col);
                float2 ssh = *(const float2*)(scshp + col);
#pragma unroll
                for (int h = 0; h < 2; h++) {
                    int rl = wm * 32 + mt2 * 16 + g + h * 8;
                    size_t id = (size_t)(bm + rl) * 256 + col;
                    float2 rr = *(const float2*)(retr + id);
                    float2 xx = *(const float2*)(xfp + id);
                    float2 sv = *(const float2*)(scvp + id);
                    float g0 = acc[mt2][nt2][h * 2 + 0] + bv.x;
                    float g1 = acc[mt2][nt2][h * 2 + 1] + bv.y;
                    g0 = 1.f / (1.f + expf(-g0));
                    g1 = 1.f / (1.f + expf(-g1));
                    float mo0 = g0 * rr.x + (1.f - g0) * xx.x;
                    float mo1 = g1 * rr.y + (1.f - g1) * xx.y;
                    float s0 = (0.1f * mo0 >= 1.f) ? 1.f : 0.f;
                    float s1 = (0.1f * mo1 >= 1.f) ? 1.f : 0.f;
                    T[(cl + 0) * 129 + rl] = fmaxf(s0 + sv.x * ssc.x + ssh.x, 0.f);
                    T[(cl + 1) * 129 + rl] = fmaxf(s1 + sv.y * ssc.y + ssh.y, 0.f);
                }
            }
        }
        __syncthreads();
        int c = tid >> 2, q = tid & 3;
        int b = bm >> 10, p0 = bm & 1023;
        float* ob = outp + ((size_t)b * 256 + bn + c) * 1024 + p0;
        const float* tr = T + c * 129;
#pragma unroll
        for (int i = 0; i < 8; i++) {
            int j4 = (q + i * 4) * 4;
            float4 w4 = make_float4(tr[j4], tr[j4 + 1], tr[j4 + 2], tr[j4 + 3]);
            *(float4*)(ob + j4) = w4;
        }
        return;
    }

    // normal epilogue
#pragma unroll
    for (int mt2 = 0; mt2 < 2; mt2++) {
#pragma unroll
        for (int nt2 = 0; nt2 < NTW; nt2++) {
            int row0 = bm + wm * 32 + mt2 * 16 + g;
            int col  = bn + wn * (NTW * 8) + nt2 * 8 + t4 * 2;
            float2 bv = (flags & F_BIAS) ? *(const float2*)(bias + col)
                                         : make_float2(0.f, 0.f);
#pragma unroll
            for (int h = 0; h < 2; h++) {
                float v0 = acc[mt2][nt2][h * 2 + 0] * alpha + bv.x;
                float v1 = acc[mt2][nt2][h * 2 + 1] * alpha + bv.y;
                if (flags & F_RELU) { v0 = fmaxf(v0, 0.f); v1 = fmaxf(v1, 0.f); }
                if (flags & F_SIG) {
                    v0 = 1.f / (1.f + expf(-v0));
                    v1 = 1.f / (1.f + expf(-v1));
                }
                if (flags & F_TF32) { v0 = tf32f(v0); v1 = tf32f(v1); }
                *(float2*)(Cc + (size_t)(row0 + h * 8) * N + col) = make_float2(v0, v1);
            }
        }
    }
}

// ---------------------------------------------------------------------------
// NCHW -> NHWC transpose (x, C=128), output tf32-rounded
// ---------------------------------------------------------------------------
__global__ void k_nchw_to_nhwc(const float* __restrict__ src, float* __restrict__ dst, int C)
{
    __shared__ float tile[32][33];
    int b  = blockIdx.x >> 5;
    int p0 = (blockIdx.x & 31) << 5;
    int c0 = blockIdx.y << 5;
    for (int i = threadIdx.y; i < 32; i += 8)
        tile[i][threadIdx.x] = src[((size_t)b * C + c0 + i) * HWP + p0 + threadIdx.x];
    __syncthreads();
    for (int i = threadIdx.y; i < 32; i += 8)
        dst[((size_t)(b << 10) + p0 + i) * C + c0 + threadIdx.x] = tf32f(tile[threadIdx.x][i]);
}

// ---------------------------------------------------------------------------
// Merged weight prep: conv reorders (tap-major K) + plain tf32 rounds.
// Linear index ranges: [0,n1) w1 reorder, [n1,n1+n2) w2 reorder, then rounds.
// ---------------------------------------------------------------------------
__global__ void k_prep(const float* __restrict__ w1, float* __restrict__ w1r,
                       const float* __restrict__ w2, float* __restrict__ w2r,
                       const float* __restrict__ c1, float* __restrict__ c1r,
                       const float* __restrict__ gw, float* __restrict__ gwr,
                       const float* __restrict__ sw, float* __restrict__ swr)
{
    const int n1 = COUT * CIN * 9;        // 294912
    const int n2 = COUT * COUT * 9;       // 589824
    const int n3 = COUT * COUT;           // 65536
    const int n4 = COUT * 2 * COUT;       // 262144? no: 256*512 = 131072
    int idx = blockIdx.x * 256 + threadIdx.x;
    if (idx < n1) {
        int n = idx / (CIN * 9), rem = idx - n * (CIN * 9);
        int ic = rem / 9, tap = rem - ic * 9;
        w1r[(size_t)n * CIN * 9 + tap * CIN + ic] = tf32f(w1[idx]);
        return;
    }
    idx -= n1;
    if (idx < n2) {
        int n = idx / (COUT * 9), rem = idx - n * (COUT * 9);
        int ic = rem / 9, tap = rem - ic * 9;
        w2r[(size_t)n * COUT * 9 + tap * COUT + ic] = tf32f(w2[idx]);
        return;
    }
    idx -= n2;
    if (idx < n3) { c1r[idx] = tf32f(c1[idx]); return; }
    idx -= n3;
    if (idx < COUT * 2 * CIN * 2) { gwr[idx] = tf32f(gw[idx]); return; }  // 131072
    idx -= COUT * 2 * CIN * 2;
    if (idx < COUT * CIN) swr[idx] = tf32f(sw[idx]);
    (void)n4;
}

// ---------------------------------------------------------------------------
// Fold mem_keys into ctrl_w2: KW[j,k] = sum_c keys[j,c]*W2[c,k] (tf32),
// kb[j] = (keys[j,:] . b2) / 16
// ---------------------------------------------------------------------------
__global__ void k_keyfold(const float* __restrict__ keys, const float* __restrict__ W2,
                          const float* __restrict__ b2,
                          float* __restrict__ KW, float* __restrict__ kb)
{
    __shared__ float krow[256];
    __shared__ float red[256];
    int j = blockIdx.x, t = threadIdx.x;
    krow[t] = keys[j * 256 + t];
    __syncthreads();
    float acc = 0.f;
    for (int c = 0; c < 256; c++) acc += krow[c] * W2[c * 256 + t];
    KW[j * 256 + t] = tf32f(acc);
    red[t] = krow[t] * b2[t];
    __syncthreads();
    for (int o = 128; o; o >>= 1) { if (t < o) red[t] += red[t + o]; __syncthreads(); }
    if (t == 0) kb[j] = red[0] * (1.f / 16.f);
}

// ---------------------------------------------------------------------------
// Deterministic BN stats (two stage), 256 channels NHWC
// ---------------------------------------------------------------------------
__global__ void k_bn_partial(const float* __restrict__ t, float* __restrict__ psum,
                             float* __restrict__ psq)
{
    int c = threadIdx.x;
    int r0 = blockIdx.x * 128;
    float s = 0.f, s2 = 0.f;
    for (int r = 0; r < 128; r++) {
        float v = t[(size_t)(r0 + r) * 256 + c];
        s += v; s2 += v * v;
    }
    psum[blockIdx.x * 256 + c] = s;
    psq [blockIdx.x * 256 + c] = s2;
}

__global__ void k_bn_finalize(const float* __restrict__ psum, const float* __restrict__ psq,
                              const float* __restrict__ gamma, const float* __restrict__ beta,
                              float* __restrict__ scale, float* __restrict__ shift)
{
    int c = threadIdx.x;
    float s = 0.f, s2 = 0.f;
    for (int i = 0; i < 256; i++) { s += psum[i * 256 + c]; s2 += psq[i * 256 + c]; }
    float mean = s / 32768.f;
    float var  = s2 / 32768.f - mean * mean;
    float sc   = gamma[c] * rsqrtf(var + EPSBN);
    scale[c] = sc;
    shift[c] = beta[c] - mean * sc;
}

// t1b = tf32(relu(t1*sc + sh))
__global__ void k_bnrelu(const float* __restrict__ t, const float* __restrict__ scale,
                         const float* __restrict__ shift, float* __restrict__ o)
{
    int idx = blockIdx.x * 256 + threadIdx.x;   // MROWS*64 float4s
    int c4 = idx & 63;
    float4 v  = ((const float4*)t)[idx];
    float4 sc = ((const float4*)scale)[c4];
    float4 sh = ((const float4*)shift)[c4];
    v.x = tf32f(fmaxf(v.x * sc.x + sh.x, 0.f));
    v.y = tf32f(fmaxf(v.y * sc.y + sh.y, 0.f));
    v.z = tf32f(fmaxf(v.z * sc.z + sh.z, 0.f));
    v.w = tf32f(fmaxf(v.w * sc.w + sh.w, 0.f));
    ((float4*)o)[idx] = v;
}

// ---------------------------------------------------------------------------
// Channel attention (BN2 fused: v = t2*sc + sh)
// ---------------------------------------------------------------------------
__global__ void k_ca_pool_partial(const float* __restrict__ t2,
                                  const float* __restrict__ bsc, const float* __restrict__ bsh,
                                  float* __restrict__ pavg, float* __restrict__ pmax)
{
    int b = blockIdx.x >> 3, ch = blockIdx.x & 7;
    int c = threadIdx.x;
    float scv = bsc[c], shv = bsh[c];
    float s = 0.f, mx = -1e30f;
    for (int p = 0; p < 128; p++) {
        float v = t2[((size_t)(b << 10) + (ch << 7) + p) * 256 + c] * scv + shv;
        s += v; mx = fmaxf(mx, v);
    }
    pavg[blockIdx.x * 256 + c] = s;
    pmax[blockIdx.x * 256 + c] = mx;
}

__global__ void k_ca_mlp(const float* __restrict__ pavg, const float* __restrict__ pmax,
                         const float* __restrict__ w1, const float* __restrict__ w2,
                         float* __restrict__ catt)
{
    __shared__ float av[256], mx[256], h[32];
    int b = blockIdx.x, c = threadIdx.x;
    float s = 0.f, m = -1e30f;
    for (int i = 0; i < 8; i++) {
        s += pavg[(b * 8 + i) * 256 + c];
        m = fmaxf(m, pmax[(b * 8 + i) * 256 + c]);
    }
    av[c] = s / 1024.f; mx[c] = m;
    __syncthreads();
    if (c < 32) {
        const float* src = (c < 16) ? av : mx;
        int j = c & 15;
        float acc = 0.f;
        for (int k = 0; k < 256; k++) acc += w1[j * 256 + k] * src[k];
        h[c] = fmaxf(acc, 0.f);
    }
    __syncthreads();
    float acc = 0.f;
#pragma unroll
    for (int j = 0; j < 16; j++) acc += w2[c * 16 + j] * (h[j] + h[16 + j]);
    catt[b * 256 + c] = 1.f / (1.f + expf(-acc));
}

// ---------------------------------------------------------------------------
// Spatial attention (BN2 fused)
// ---------------------------------------------------------------------------
__global__ void k_sp_pool(const float* __restrict__ t2,
                          const float* __restrict__ bsc, const float* __restrict__ bsh,
                          const float* __restrict__ catt,
                          float* __restrict__ spm, float* __restrict__ spx)
{
    int warp = threadIdx.x >> 5, lane = threadIdx.x & 31;
    int m = blockIdx.x * 8 + warp;
    int b = m >> 10;
    float s = 0.f, mx = -1e30f;
#pragma unroll
    for (int i = 0; i < 8; i++) {
        int c = i * 32 + lane;
        float v = (t2[(size_t)m * 256 + c] * bsc[c] + bsh[c]) * catt[b * 256 + c];
        s += v; mx = fmaxf(mx, v);
    }
    for (int o = 16; o; o >>= 1) {
        s += __shfl_xor_sync(0xffffffffu, s, o);
        mx = fmaxf(mx, __shfl_xor_sync(0xffffffffu, mx, o));
    }
    if (lane == 0) { spm[m] = s / 256.f; spx[m] = mx; }
}

__global__ void k_sa_conv(const float* __restrict__ spm, const float* __restrict__ spx,
                          const float* __restrict__ saw, const float* __restrict__ sab,
                          float* __restrict__ sa)
{
    __shared__ float sm[1024], sx[1024], w[98];
    int b = blockIdx.x, t = threadIdx.x;
    for (int i = t; i < 1024; i += 256) { sm[i] = spm[b * 1024 + i]; sx[i] = spx[b * 1024 + i]; }
    if (t < 98) w[t] = saw[t];
    __syncthreads();
    float bias = sab[0];
    for (int i = t; i < 1024; i += 256) {
        int y = i >> 5, x = i & 31;
        float acc = bias;
#pragma unroll
        for (int ky = 0; ky < 7; ky++) {
            int yy = y + ky - 3; if ((unsigned)yy >= 32u) continue;
#pragma unroll
            for (int kx = 0; kx < 7; kx++) {
                int xx = x + kx - 3; if ((unsigned)xx >= 32u) continue;
                acc += w[ky * 7 + kx] * sm[yy * 32 + xx] + w[49 + ky * 7 + kx] * sx[yy * 32 + xx];
            }
        }
        sa[b * 1024 + i] = 1.f / (1.f + expf(-acc));
    }
}

// xf = tf32( (t2*bsc+bsh) * catt * sa )
__global__ void k_apply_att(const float* __restrict__ t2,
                            const float* __restrict__ bsc, const float* __restrict__ bsh,
                            const float* __restrict__ catt,
                            const float* __restrict__ sa, float* __restrict__ xf)
{
    int idx = blockIdx.x * 256 + threadIdx.x;
    int m = idx >> 6, c4 = idx & 63;
    int b = m >> 10;
    float s = sa[m];
    float4 v  = ((const float4*)t2)[idx];
    float4 sc = ((const float4*)bsc)[c4];
    float4 sh = ((const float4*)bsh)[c4];
    float4 ca = ((const float4*)(catt + b * 256))[c4];
    v.x = tf32f((v.x * sc.x + sh.x) * ca.x * s);
    v.y = tf32f((v.y * sc.y + sh.y) * ca.y * s);
    v.z = tf32f((v.z * sc.z + sh.z) * ca.z * s);
    v.w = tf32f((v.w * sc.w + sh.w) * ca.w * s);
    ((float4*)xf)[idx] = v;
}

// ---------------------------------------------------------------------------
// Fused softmax over 64 logits + retrieved = attn @ mem.
// 512 threads, 16 warps x 4 rows each => 64 rows per block, 512 blocks.
// ---------------------------------------------------------------------------
__global__ void __launch_bounds__(512)
k_softmax_retrieve(const float* __restrict__ L, const float* __restrict__ mem,
                   float* __restrict__ retr)
{
    extern __shared__ float ms[];
    for (int i = threadIdx.x; i < 16384; i += 512) ms[i] = mem[i];
    __syncthreads();
    int warp = threadIdx.x >> 5, lane = threadIdx.x & 31;
    int m0 = blockIdx.x * 64 + warp * 4;
    for (int rr = 0; rr < 4; rr++) {
        int m = m0 + rr;
        float l0 = L[(size_t)m * 64 + lane];
        float l1 = L[(size_t)m * 64 + 32 + lane];
        float mx = fmaxf(l0, l1);
        for (int o = 16; o; o >>= 1) mx = fmaxf(mx, __shfl_xor_sync(0xffffffffu, mx, o));
        float e0 = expf(l0 - mx), e1 = expf(l1 - mx);
        float s = e0 + e1;
        for (int o = 16; o; o >>= 1) s += __shfl_xor_sync(0xffffffffu, s, o);
        float inv = 1.f / s;
        e0 *= inv; e1 *= inv;
        float acc[8] = {};
        for (int j = 0; j < 32; j++) {
            float a0 = __shfl_sync(0xffffffffu, e0, j);
            float a1 = __shfl_sync(0xffffffffu, e1, j);
#pragma unroll
            for (int f = 0; f < 8; f++)
                acc[f] += a0 * ms[j * 256 + f * 32 + lane] + a1 * ms[(j + 32) * 256 + f * 32 + lane];
        }
#pragma unroll
        for (int f = 0; f < 8; f++)
            retr[(size_t)m * 256 + f * 32 + lane] = tf32f(acc[f]);
    }
}

// ---------------------------------------------------------------------------
// Launch
// ---------------------------------------------------------------------------
extern "C" void kernel_launch(void* const* d_in, const int* in_sizes, int n_in,
                              void* d_out, int out_size)
{
    const float* x        = (const float*)d_in[0];
    const float* conv1_w  = (const float*)d_in[1];
    const float* conv1_b  = (const float*)d_in[2];
    const float* bn1_g    = (const float*)d_in[3];
    const float* bn1_b    = (const float*)d_in[4];
    const float* conv2_w  = (const float*)d_in[5];
    const float* conv2_b  = (const float*)d_in[6];
    const float* bn2_g    = (const float*)d_in[7];
    const float* bn2_b    = (const float*)d_in[8];
    const float* ca_w1    = (const float*)d_in[9];
    const float* ca_w2    = (const float*)d_in[10];
    const float* sa_w     = (const float*)d_in[11];
    const float* sa_b     = (const float*)d_in[12];
    const float* memv     = (const float*)d_in[13];
    const float* mem_keys = (const float*)d_in[14];
    const float* ctrl_w1  = (const float*)d_in[15];
    const float* ctrl_b1  = (const float*)d_in[16];
    const float* ctrl_w2  = (const float*)d_in[17];
    const float* ctrl_b2  = (const float*)d_in[18];
    const float* gate_w   = (const float*)d_in[19];
    const float* gate_b   = (const float*)d_in[20];
    const float* sc_w     = (const float*)d_in[21];
    const float* sc_g     = (const float*)d_in[22];
    const float* sc_b     = (const float*)d_in[23];
    float* out = (float*)d_out;

    void* basep = nullptr;
    cudaGetSymbolAddress(&basep, g_scratch);
    float* S = (float*)basep;

    float* xn    = S + OFF_XN;
    float* t1    = S + OFF_T1;
    float* t2    = S + OFF_T2;
    float* xf    = S + OFF_XF;
    float* retr  = S + OFF_RETR;
    float* t1b   = S + OFF_T1B;
    float* scv   = S + OFF_SCV;
    float* Lbuf  = S + OFF_L;
    float* w1r   = S + OFF_W1R;
    float* w2r   = S + OFF_W2R;
    float* w3r   = S + OFF_W3R;
    float* wgr   = S + OFF_WGR;
    float* wscr  = S + OFF_WSCR;
    float* KW    = S + OFF_KW;
    float* kb    = S + OFF_KB;
    float* psum  = S + OFF_PSUM;
    float* psq   = S + OFF_PSQ;
    float* pavg  = S + OFF_PAVG;
    float* pmax  = S + OFF_PMAX;
    float* catt  = S + OFF_CATT;
    float* spm   = S + OFF_SPM;
    float* spx   = S + OFF_SPX;
    float* sa    = S + OFF_SA;
    float* bn1sc = S + OFF_BN1SC;  float* bn1sh = S + OFF_BN1SH;
    float* bn2sc = S + OFF_BN2SC;  float* bn2sh = S + OFF_BN2SH;
    float* scsc  = S + OFF_SCSC;   float* scsh  = S + OFF_SCSH;

    const int dyn128 = 2 * (32 * 132 + 64 * 66) * 4;   // 67584
    const int dyn64  = 2 * (32 * 132 + 32 * 66) * 4;   // 50688
    cudaFuncSetAttribute(k_mma<128>, cudaFuncAttributeMaxDynamicSharedMemorySize, dyn128);
    cudaFuncSetAttribute(k_mma<64>,  cudaFuncAttributeMaxDynamicSharedMemorySize, dyn64);
    cudaFuncSetAttribute(k_softmax_retrieve, cudaFuncAttributeMaxDynamicSharedMemorySize, 65536);

    dim3 tb32x8(32, 8);
    dim3 g2(MROWS / 128, 2);   // N=256 tiles
    dim3 g1(MROWS / 128, 1);   // N=64 tiles

    // 1) x -> NHWC (tf32-rounded)
    k_nchw_to_nhwc<<<dim3(BB * 32, CIN / 32), tb32x8>>>(x, xn, CIN);

    // 2) merged weight prep + key-fold
    k_prep<<<4352, 256>>>(conv1_w, w1r, conv2_w, w2r, ctrl_w1, w3r, gate_w, wgr, sc_w, wscr);
    k_keyfold<<<MEMN, 256>>>(mem_keys, ctrl_w2, ctrl_b2, KW, kb);

    // 3) conv1: implicit im2col GEMM (+bias, tf32 out) -> t1
    k_mma<128><<<g2, 512, dyn128>>>(xn, nullptr, 1 << 30, 0, 0, 7,
                                    w1r, 9 * CIN, t1, conv1_b,
                                    COUT, 9 * CIN, 1.f, F_BIAS | F_TF32,
                                    nullptr, nullptr, nullptr, nullptr, nullptr, nullptr);

    // 4) BN1 stats + bnrelu pass -> t1b (rounded)
    k_bn_partial<<<256, 256>>>(t1, psum, psq);
    k_bn_finalize<<<1, 256>>>(psum, psq, bn1_g, bn1_b, bn1sc, bn1sh);
    k_bnrelu<<<MROWS * 64 / 256, 256>>>(t1, bn1sc, bn1sh, t1b);

    // 5) conv2: implicit im2col GEMM over t1b (+bias) -> t2 (raw)
    k_mma<128><<<g2, 512, dyn128>>>(t1b, nullptr, 1 << 30, 0, 0, 8,
                                    w2r, 9 * COUT, t2, conv2_b,
                                    COUT, 9 * COUT, 1.f, F_BIAS,
                                    nullptr, nullptr, nullptr, nullptr, nullptr, nullptr);

    // 6) BN2 stats (apply fused into downstream consumers)
    k_bn_partial<<<256, 256>>>(t2, psum, psq);
    k_bn_finalize<<<1, 256>>>(psum, psq, bn2_g, bn2_b, bn2sc, bn2sh);

    // 7) channel attention (BN2 fused)
    k_ca_pool_partial<<<BB * 8, 256>>>(t2, bn2sc, bn2sh, pavg, pmax);
    k_ca_mlp<<<BB, 256>>>(pavg, pmax, ca_w1, ca_w2, catt);

    // 8) spatial attention (BN2 fused) -> xf (rounded)
    k_sp_pool<<<MROWS / 8, 256>>>(t2, bn2sc, bn2sh, catt, spm, spx);
    k_sa_conv<<<BB, 256>>>(spm, spx, sa_w, sa_b, sa);
    k_apply_att<<<MROWS * 64 / 256, 256>>>(t2, bn2sc, bn2sh, catt, sa, xf);

    // 9) memory module
    //   h1 = relu(xf @ ctrl_w1^T + b1) -> t1 (rounded)
    k_mma<128><<<g2, 512, dyn128>>>(xf, nullptr, 1 << 30, COUT, 0, 0,
                                    w3r, COUT, t1, ctrl_b1,
                                    COUT, COUT, 1.f, F_BIAS | F_RELU | F_TF32,
                                    nullptr, nullptr, nullptr, nullptr, nullptr, nullptr);
    //   logits = (h1 @ KW^T)/16 + kb  (q-GEMM folded into KW)
    k_mma<64><<<g1, 512, dyn64>>>(t1, nullptr, 1 << 30, COUT, 0, 0,
                                  KW, COUT, Lbuf, kb,
                                  MEMN, COUT, 1.f / 16.f, F_BIAS,
                                  nullptr, nullptr, nullptr, nullptr, nullptr, nullptr);
    k_softmax_retrieve<<<MROWS / 64, 512, 65536>>>(Lbuf, memv, retr);

    // 10) shortcut 1x1 conv + BN stats (must precede fused gate-final)
    k_mma<128><<<g2, 512, dyn128>>>(xn, nullptr, 1 << 30, CIN, 0, 0,
                                    wscr, CIN, scv, nullptr,
                                    COUT, CIN, 1.f, 0,
                                    nullptr, nullptr, nullptr, nullptr, nullptr, nullptr);
    k_bn_partial<<<256, 256>>>(scv, psum, psq);
    k_bn_finalize<<<1, 256>>>(psum, psq, sc_g, sc_b, scsc, scsh);

    // 11) gate GEMM with fused final epilogue -> out (NCHW)
    k_mma<128><<<g2, 512, dyn128>>>(xf, retr, COUT, COUT, COUT, 0,
                                    wgr, 2 * COUT, nullptr, gate_b,
                                    COUT, 2 * COUT, 1.f, F_BIAS | F_SIG | F_FINAL,
                                    retr, xf, scv, scsc, scsh, out);
}

// round 10
// speedup vs baseline: 1.5799x; 1.5799x over previous
#include <cuda_runtime.h>
#include <cuda_fp16.h>
#include <cstdint>
#include <cstddef>

// ---------------------------------------------------------------------------
// Problem constants
// ---------------------------------------------------------------------------
#define BB    32
#define CIN   128
#define COUT  256
#define HH    32
#define WW    32
#define HWP   1024              // H*W
#define MROWS 32768             // B*H*W
#define MEMN  64
#define EPSBN 1e-5f

// ---------------------------------------------------------------------------
// Scratch (single __device__ array; offsets in FLOAT units)
// Half buffers live inside float-sized slots (only first half used).
// ---------------------------------------------------------------------------
#define OFF_XN     0ull                      // half[32768*128]
#define OFF_T1     4194304ull                // float[32768*256]
#define OFF_T2     12582912ull               // float
#define OFF_XF     20971520ull               // half
#define OFF_RETR   29360128ull               // half
#define OFF_T1B    37748736ull               // half (bn1relu(t1)) ; also h1 half
#define OFF_SCV    46137344ull               // float
#define OFF_L      54525952ull               // float[32768*64]
#define OFF_W1R    56623104ull               // half[256*1152]
#define OFF_W2R    56918016ull               // half[256*2304]
#define OFF_W3R    57507840ull               // half[256*256]
#define OFF_WGR    57573376ull               // half[256*512]
#define OFF_WSCR   57704448ull               // half[256*128]
#define OFF_KW     57737216ull               // half[64*256]
#define OFF_KB     57753600ull               // float[64] (padded)
#define OFF_PSUM   57753856ull               // float[256*256]
#define OFF_PSQ    57819392ull
#define OFF_PAVG   57884928ull
#define OFF_PMAX   57950464ull
#define OFF_CATT   58016000ull               // 32*256
#define OFF_SPM    58024192ull               // 32768
#define OFF_SPX    58056960ull
#define OFF_SA     58089728ull
#define OFF_BN1SC  58122496ull               // 256 each
#define OFF_BN1SH  58122752ull
#define OFF_BN2SC  58123008ull
#define OFF_BN2SH  58123264ull
#define OFF_SCSC   58123520ull
#define OFF_SCSH   58123776ull
#define SCRATCH_TOTAL 58124032ull

__device__ float g_scratch[SCRATCH_TOTAL];

// ---------------------------------------------------------------------------
// fp16 MMA helper (plain sm_80+ PTX — compiles for sm_103 non-"a" target)
// ---------------------------------------------------------------------------
__device__ __forceinline__ void mma_f16(float* d, const uint32_t* a, const uint32_t* b) {
    asm volatile(
        "mma.sync.aligned.m16n8k16.row.col.f32.f16.f16.f32 "
        "{%0,%1,%2,%3}, {%4,%5,%6,%7}, {%8,%9}, {%0,%1,%2,%3};"
        : "+f"(d[0]), "+f"(d[1]), "+f"(d[2]), "+f"(d[3])
        : "r"(a[0]), "r"(a[1]), "r"(a[2]), "r"(a[3]), "r"(b[0]), "r"(b[1]));
}

// ---------------------------------------------------------------------------
// fp16 tensor-core GEMM, 512 threads, 4x4 warp grid, 32x32 warp tile, BK=32.
//   C[M,N] = alpha * A[M,K] * Wt[N,K]^T  (+bias)(relu|sigmoid)(half-out)(final)
// A/B are __half (pre-converted). c4shift>0 => implicit im2col 3x3 pad1 NHWC.
// F_FINAL (gate GEMM, BN=128): epilogue computes mo/spike/shortcut-BN/ReLU and
// writes NCHW-transposed to outp.
// ---------------------------------------------------------------------------
#define F_BIAS  1
#define F_RELU  2
#define F_SIG   8
#define F_HALF  16
#define F_FINAL 32

template<int BN>
__global__ void __launch_bounds__(512, 2)
k_mma(const __half* __restrict__ A, const __half* __restrict__ A2, int Ksplit,
      int lda, int lda2, int c4shift,
      const __half* __restrict__ Wt, int ldw,
      void* __restrict__ Cc, const float* __restrict__ bias,
      int N, int K, float alpha, int flags,
      const __half* __restrict__ retr, const __half* __restrict__ xfp,
      const float* __restrict__ scvp,
      const float* __restrict__ scscp, const float* __restrict__ scshp,
      float* __restrict__ outp)
{
    constexpr int NTW = BN / 32;                  // n-tiles (8 cols) per warp
    constexpr int ASZ = 16 * 132;                 // A stage words (16 tiles)
    constexpr int BSZ = (BN / 8) * 2 * 66;        // B stage words
    constexpr int STG = ASZ + BSZ;

    extern __shared__ __align__(16) uint32_t dsm[];

    const int tid  = threadIdx.x;
    const int lane = tid & 31;
    const int wid  = tid >> 5;
    const int wm   = wid & 3;
    const int wn   = wid >> 2;
    const int bm   = blockIdx.x * 128;
    const int bn   = blockIdx.y * BN;

    float acc[2][NTW][4];
#pragma unroll
    for (int i = 0; i < 2; i++)
#pragma unroll
        for (int j = 0; j < NTW; j++)
#pragma unroll
            for (int q = 0; q < 4; q++) acc[i][j][q] = 0.f;

    uint4 Areg;
    uint4 Breg;

    const int r  = tid >> 2;        // 0..127
    const int c8 = tid & 3;         // 8-half chunk
    const bool bAct = (BN == 128) || (tid < 256);

    auto loadA = [&](int k0) {
        int kg = k0 + (c8 << 3);
        uint4 v = make_uint4(0u, 0u, 0u, 0u);
        if (c4shift) {
            int tap = kg >> c4shift;
            int ic  = kg & ((1 << c4shift) - 1);
            int t3  = tap / 3;
            int m   = bm + r;
            int yy  = ((m >> 5) & 31) + t3 - 1;
            int xx  = (m & 31) + (tap - t3 * 3) - 1;
            if ((unsigned)yy < 32u && (unsigned)xx < 32u)
                v = *(const uint4*)(A +
                    (((size_t)((m >> 10) << 10) + (yy << 5) + xx) << c4shift) + ic);
        } else {
            const __half* p;
            if (kg < Ksplit) p = A  + (size_t)(bm + r) * lda  + kg;
            else             p = A2 + (size_t)(bm + r) * lda2 + (kg - Ksplit);
            v = *(const uint4*)p;
        }
        Areg = v;
    };

    auto loadB = [&](int k0) {
        if (bAct)
            Breg = *(const uint4*)(Wt + (size_t)(bn + r) * ldw + k0 + (c8 << 3));
    };

    auto stsA = [&](int st) {
        int mt = r >> 4, rp = r & 15, kt = c8 >> 1;
        int w  = ((c8 & 1) << 1) + (rp >> 3);
        uint32_t* tp = dsm + st * STG + (mt * 2 + kt) * 132 + (rp & 7) * 16 + w;
        tp[0]  = Areg.x;
        tp[4]  = Areg.y;
        tp[8]  = Areg.z;
        tp[12] = Areg.w;
    };

    auto stsB = [&](int st) {
        if (!bAct) return;
        int nt = r >> 3, cp = r & 7, kt = c8 >> 1;
        int w  = c8 & 1;
        uint32_t* tp = dsm + st * STG + ASZ + (nt * 2 + kt) * 66 + cp * 8 + w;
        tp[0] = Breg.x;
        tp[2] = Breg.y;
        tp[4] = Breg.z;
        tp[6] = Breg.w;
    };

    auto compute = [&](int st) {
        const uint32_t* sA = dsm + st * STG;
        const uint32_t* sB = sA + ASZ;
#pragma unroll
        for (int kt = 0; kt < 2; kt++) {
            uint32_t af[2][4];
#pragma unroll
            for (int mt2 = 0; mt2 < 2; mt2++)
                *(uint4*)af[mt2] =
                    *(const uint4*)(sA + ((wm * 2 + mt2) * 2 + kt) * 132 + lane * 4);
            uint32_t bf[NTW][2];
#pragma unroll
            for (int nt2 = 0; nt2 < NTW; nt2++)
                *(uint2*)bf[nt2] =
                    *(const uint2*)(sB + ((wn * NTW + nt2) * 2 + kt) * 66 + lane * 2);
#pragma unroll
            for (int mt2 = 0; mt2 < 2; mt2++)
#pragma unroll
                for (int nt2 = 0; nt2 < NTW; nt2++)
                    mma_f16(acc[mt2][nt2], af[mt2], bf[nt2]);
        }
    };

    const int nIter = K >> 5;
    loadA(0); loadB(0);
    stsA(0);  stsB(0);
    if (nIter > 1) { loadA(32); loadB(32); }
    __syncthreads();
    for (int it = 0; it < nIter; ++it) {
        if (it + 1 < nIter) { stsA((it + 1) & 1); stsB((it + 1) & 1); }
        if (it + 2 < nIter) { loadA((it + 2) << 5); loadB((it + 2) << 5); }
        compute(it & 1);
        __syncthreads();
    }

    const int g = lane >> 2, t4 = lane & 3;

    if (flags & F_FINAL) {
        // fused gate->final epilogue (BN==128 path only)
        float* T = (float*)dsm;   // 128 x 128 tile, col stride 129
#pragma unroll
        for (int mt2 = 0; mt2 < 2; mt2++) {
#pragma unroll
            for (int nt2 = 0; nt2 < NTW; nt2++) {
                int cl = wn * (NTW * 8) + nt2 * 8 + t4 * 2;
                int col = bn + cl;
                float2 bv  = *(const float2*)(bias + col);
                float2 ssc = *(const float2*)(scscp + col);
                float2 ssh = *(const float2*)(scshp + col);
#pragma unroll
                for (int h = 0; h < 2; h++) {
                    int rl = wm * 32 + mt2 * 16 + g + h * 8;
                    size_t id = (size_t)(bm + rl) * 256 + col;
                    float2 rr = __half22float2(*(const __half2*)(retr + id));
                    float2 xx = __half22float2(*(const __half2*)(xfp + id));
                    float2 sv = *(const float2*)(scvp + id);
                    float g0 = acc[mt2][nt2][h * 2 + 0] + bv.x;
                    float g1 = acc[mt2][nt2][h * 2 + 1] + bv.y;
                    g0 = 1.f / (1.f + expf(-g0));
                    g1 = 1.f / (1.f + expf(-g1));
                    float mo0 = g0 * rr.x + (1.f - g0) * xx.x;
                    float mo1 = g1 * rr.y + (1.f - g1) * xx.y;
                    float s0 = (0.1f * mo0 >= 1.f) ? 1.f : 0.f;
                    float s1 = (0.1f * mo1 >= 1.f) ? 1.f : 0.f;
                    T[(cl + 0) * 129 + rl] = fmaxf(s0 + sv.x * ssc.x + ssh.x, 0.f);
                    T[(cl + 1) * 129 + rl] = fmaxf(s1 + sv.y * ssc.y + ssh.y, 0.f);
                }
            }
        }
        __syncthreads();
        int c = tid >> 2, q = tid & 3;
        int b = bm >> 10, p0 = bm & 1023;
        float* ob = outp + ((size_t)b * 256 + bn + c) * 1024 + p0;
        const float* tr = T + c * 129;
#pragma unroll
        for (int i = 0; i < 8; i++) {
            int j4 = (q + i * 4) * 4;
            float4 w4 = make_float4(tr[j4], tr[j4 + 1], tr[j4 + 2], tr[j4 + 3]);
            *(float4*)(ob + j4) = w4;
        }
        return;
    }

    // normal epilogue
#pragma unroll
    for (int mt2 = 0; mt2 < 2; mt2++) {
#pragma unroll
        for (int nt2 = 0; nt2 < NTW; nt2++) {
            int row0 = bm + wm * 32 + mt2 * 16 + g;
            int col  = bn + wn * (NTW * 8) + nt2 * 8 + t4 * 2;
            float2 bv = (flags & F_BIAS) ? *(const float2*)(bias + col)
                                         : make_float2(0.f, 0.f);
#pragma unroll
            for (int h = 0; h < 2; h++) {
                float v0 = acc[mt2][nt2][h * 2 + 0] * alpha + bv.x;
                float v1 = acc[mt2][nt2][h * 2 + 1] * alpha + bv.y;
                if (flags & F_RELU) { v0 = fmaxf(v0, 0.f); v1 = fmaxf(v1, 0.f); }
                if (flags & F_SIG) {
                    v0 = 1.f / (1.f + expf(-v0));
                    v1 = 1.f / (1.f + expf(-v1));
                }
                size_t id = (size_t)(row0 + h * 8) * N + col;
                if (flags & F_HALF)
                    *(__half2*)((__half*)Cc + id) = __floats2half2_rn(v0, v1);
                else
                    *(float2*)((float*)Cc + id) = make_float2(v0, v1);
            }
        }
    }
}

// ---------------------------------------------------------------------------
// NCHW -> NHWC transpose (x, C=128), output half
// ---------------------------------------------------------------------------
__global__ void k_nchw_to_nhwc(const float* __restrict__ src, __half* __restrict__ dst, int C)
{
    __shared__ float tile[32][33];
    int b  = blockIdx.x >> 5;
    int p0 = (blockIdx.x & 31) << 5;
    int c0 = blockIdx.y << 5;
    for (int i = threadIdx.y; i < 32; i += 8)
        tile[i][threadIdx.x] = src[((size_t)b * C + c0 + i) * HWP + p0 + threadIdx.x];
    __syncthreads();
    for (int i = threadIdx.y; i < 32; i += 8)
        dst[((size_t)(b << 10) + p0 + i) * C + c0 + threadIdx.x] =
            __float2half(tile[threadIdx.x][i]);
}

// ---------------------------------------------------------------------------
// Merged weight prep: conv reorders (tap-major K) + plain half conversions
// ---------------------------------------------------------------------------
__global__ void k_prep(const float* __restrict__ w1, __half* __restrict__ w1r,
                       const float* __restrict__ w2, __half* __restrict__ w2r,
                       const float* __restrict__ c1, __half* __restrict__ c1r,
                       const float* __restrict__ gw, __half* __restrict__ gwr,
                       const float* __restrict__ sw, __half* __restrict__ swr)
{
    const int n1 = COUT * CIN * 9;        // 294912
    const int n2 = COUT * COUT * 9;       // 589824
    const int n3 = COUT * COUT;           // 65536
    const int n4 = COUT * 2 * COUT;       // 131072
    int idx = blockIdx.x * 256 + threadIdx.x;
    if (idx < n1) {
        int n = idx / (CIN * 9), rem = idx - n * (CIN * 9);
        int ic = rem / 9, tap = rem - ic * 9;
        w1r[(size_t)n * CIN * 9 + tap * CIN + ic] = __float2half(w1[idx]);
        return;
    }
    idx -= n1;
    if (idx < n2) {
        int n = idx / (COUT * 9), rem = idx - n * (COUT * 9);
        int ic = rem / 9, tap = rem - ic * 9;
        w2r[(size_t)n * COUT * 9 + tap * COUT + ic] = __float2half(w2[idx]);
        return;
    }
    idx -= n2;
    if (idx < n3) { c1r[idx] = __float2half(c1[idx]); return; }
    idx -= n3;
    if (idx < n4) { gwr[idx] = __float2half(gw[idx]); return; }
    idx -= n4;
    if (idx < COUT * CIN) swr[idx] = __float2half(sw[idx]);
}

// ---------------------------------------------------------------------------
// Fold mem_keys into ctrl_w2: KW[j,k] = sum_c keys[j,c]*W2[c,k] (half out),
// kb[j] = (keys[j,:] . b2) / 16
// ---------------------------------------------------------------------------
__global__ void k_keyfold(const float* __restrict__ keys, const float* __restrict__ W2,
                          const float* __restrict__ b2,
                          __half* __restrict__ KW, float* __restrict__ kb)
{
    __shared__ float krow[256];
    __shared__ float red[256];
    int j = blockIdx.x, t = threadIdx.x;
    krow[t] = keys[j * 256 + t];
    __syncthreads();
    float acc = 0.f;
    for (int c = 0; c < 256; c++) acc += krow[c] * W2[c * 256 + t];
    KW[j * 256 + t] = __float2half(acc);
    red[t] = krow[t] * b2[t];
    __syncthreads();
    for (int o = 128; o; o >>= 1) { if (t < o) red[t] += red[t + o]; __syncthreads(); }
    if (t == 0) kb[j] = red[0] * (1.f / 16.f);
}

// ---------------------------------------------------------------------------
// Deterministic BN stats (two stage), 256 channels NHWC
// ---------------------------------------------------------------------------
__global__ void k_bn_partial(const float* __restrict__ t, float* __restrict__ psum,
                             float* __restrict__ psq)
{
    int c = threadIdx.x;
    int r0 = blockIdx.x * 128;
    float s = 0.f, s2 = 0.f;
    for (int r = 0; r < 128; r++) {
        float v = t[(size_t)(r0 + r) * 256 + c];
        s += v; s2 += v * v;
    }
    psum[blockIdx.x * 256 + c] = s;
    psq [blockIdx.x * 256 + c] = s2;
}

__global__ void k_bn_finalize(const float* __restrict__ psum, const float* __restrict__ psq,
                              const float* __restrict__ gamma, const float* __restrict__ beta,
                              float* __restrict__ scale, float* __restrict__ shift)
{
    int c = threadIdx.x;
    float s = 0.f, s2 = 0.f;
    for (int i = 0; i < 256; i++) { s += psum[i * 256 + c]; s2 += psq[i * 256 + c]; }
    float mean = s / 32768.f;
    float var  = s2 / 32768.f - mean * mean;
    float sc   = gamma[c] * rsqrtf(var + EPSBN);
    scale[c] = sc;
    shift[c] = beta[c] - mean * sc;
}

// t1b = half(relu(t1*sc + sh))
__global__ void k_bnrelu(const float* __restrict__ t, const float* __restrict__ scale,
                         const float* __restrict__ shift, __half* __restrict__ o)
{
    int idx = blockIdx.x * 256 + threadIdx.x;   // MROWS*64 float4s
    int c4 = idx & 63;
    float4 v  = ((const float4*)t)[idx];
    float4 sc = ((const float4*)scale)[c4];
    float4 sh = ((const float4*)shift)[c4];
    float a0 = fmaxf(v.x * sc.x + sh.x, 0.f);
    float a1 = fmaxf(v.y * sc.y + sh.y, 0.f);
    float a2 = fmaxf(v.z * sc.z + sh.z, 0.f);
    float a3 = fmaxf(v.w * sc.w + sh.w, 0.f);
    __half2* op = (__half2*)(o + (size_t)idx * 4);
    op[0] = __floats2half2_rn(a0, a1);
    op[1] = __floats2half2_rn(a2, a3);
}

// ---------------------------------------------------------------------------
// Channel attention (BN2 fused: v = t2*sc + sh)
// ---------------------------------------------------------------------------
__global__ void k_ca_pool_partial(const float* __restrict__ t2,
                                  const float* __restrict__ bsc, const float* __restrict__ bsh,
                                  float* __restrict__ pavg, float* __restrict__ pmax)
{
    int b = blockIdx.x >> 3, ch = blockIdx.x & 7;
    int c = threadIdx.x;
    float scv = bsc[c], shv = bsh[c];
    float s = 0.f, mx = -1e30f;
    for (int p = 0; p < 128; p++) {
        float v = t2[((size_t)(b << 10) + (ch << 7) + p) * 256 + c] * scv + shv;
        s += v; mx = fmaxf(mx, v);
    }
    pavg[blockIdx.x * 256 + c] = s;
    pmax[blockIdx.x * 256 + c] = mx;
}

__global__ void k_ca_mlp(const float* __restrict__ pavg, const float* __restrict__ pmax,
                         const float* __restrict__ w1, const float* __restrict__ w2,
                         float* __restrict__ catt)
{
    __shared__ float av[256], mx[256], h[32];
    int b = blockIdx.x, c = threadIdx.x;
    float s = 0.f, m = -1e30f;
    for (int i = 0; i < 8; i++) {
        s += pavg[(b * 8 + i) * 256 + c];
        m = fmaxf(m, pmax[(b * 8 + i) * 256 + c]);
    }
    av[c] = s / 1024.f; mx[c] = m;
    __syncthreads();
    if (c < 32) {
        const float* src = (c < 16) ? av : mx;
        int j = c & 15;
        float acc = 0.f;
        for (int k = 0; k < 256; k++) acc += w1[j * 256 + k] * src[k];
        h[c] = fmaxf(acc, 0.f);
    }
    __syncthreads();
    float acc = 0.f;
#pragma unroll
    for (int j = 0; j < 16; j++) acc += w2[c * 16 + j] * (h[j] + h[16 + j]);
    catt[b * 256 + c] = 1.f / (1.f + expf(-acc));
}

// ---------------------------------------------------------------------------
// Spatial attention (BN2 fused)
// ---------------------------------------------------------------------------
__global__ void k_sp_pool(const float* __restrict__ t2,
                          const float* __restrict__ bsc, const float* __restrict__ bsh,
                          const float* __restrict__ catt,
                          float* __restrict__ spm, float* __restrict__ spx)
{
    int warp = threadIdx.x >> 5, lane = threadIdx.x & 31;
    int m = blockIdx.x * 8 + warp;
    int b = m >> 10;
    float s = 0.f, mx = -1e30f;
#pragma unroll
    for (int i = 0; i < 8; i++) {
        int c = i * 32 + lane;
        float v = (t2[(size_t)m * 256 + c] * bsc[c] + bsh[c]) * catt[b * 256 + c];
        s += v; mx = fmaxf(mx, v);
    }
    for (int o = 16; o; o >>= 1) {
        s += __shfl_xor_sync(0xffffffffu, s, o);
        mx = fmaxf(mx, __shfl_xor_sync(0xffffffffu, mx, o));
    }
    if (lane == 0) { spm[m] = s / 256.f; spx[m] = mx; }
}

__global__ void k_sa_conv(const float* __restrict__ spm, const float* __restrict__ spx,
                          const float* __restrict__ saw, const float* __restrict__ sab,
                          float* __restrict__ sa)
{
    __shared__ float sm[1024], sx[1024], w[98];
    int b = blockIdx.x, t = threadIdx.x;
    for (int i = t; i < 1024; i += 256) { sm[i] = spm[b * 1024 + i]; sx[i] = spx[b * 1024 + i]; }
    if (t < 98) w[t] = saw[t];
    __syncthreads();
    float bias = sab[0];
    for (int i = t; i < 1024; i += 256) {
        int y = i >> 5, x = i & 31;
        float acc = bias;
#pragma unroll
        for (int ky = 0; ky < 7; ky++) {
            int yy = y + ky - 3; if ((unsigned)yy >= 32u) continue;
#pragma unroll
            for (int kx = 0; kx < 7; kx++) {
                int xx = x + kx - 3; if ((unsigned)xx >= 32u) continue;
                acc += w[ky * 7 + kx] * sm[yy * 32 + xx] + w[49 + ky * 7 + kx] * sx[yy * 32 + xx];
            }
        }
        sa[b * 1024 + i] = 1.f / (1.f + expf(-acc));
    }
}

// xf = half( (t2*bsc+bsh) * catt * sa )
__global__ void k_apply_att(const float* __restrict__ t2,
                            const float* __restrict__ bsc, const float* __restrict__ bsh,
                            const float* __restrict__ catt,
                            const float* __restrict__ sa, __half* __restrict__ xf)
{
    int idx = blockIdx.x * 256 + threadIdx.x;
    int m = idx >> 6, c4 = idx & 63;
    int b = m >> 10;
    float s = sa[m];
    float4 v  = ((const float4*)t2)[idx];
    float4 sc = ((const float4*)bsc)[c4];
    float4 sh = ((const float4*)bsh)[c4];
    float4 ca = ((const float4*)(catt + b * 256))[c4];
    float a0 = (v.x * sc.x + sh.x) * ca.x * s;
    float a1 = (v.y * sc.y + sh.y) * ca.y * s;
    float a2 = (v.z * sc.z + sh.z) * ca.z * s;
    float a3 = (v.w * sc.w + sh.w) * ca.w * s;
    __half2* op = (__half2*)(xf + (size_t)idx * 4);
    op[0] = __floats2half2_rn(a0, a1);
    op[1] = __floats2half2_rn(a2, a3);
}

// ---------------------------------------------------------------------------
// Fused softmax over 64 logits + retrieved = attn @ mem (half out).
// 512 threads, 16 warps x 4 rows => 64 rows per block.
// ---------------------------------------------------------------------------
__global__ void __launch_bounds__(512)
k_softmax_retrieve(const float* __restrict__ L, const float* __restrict__ mem,
                   __half* __restrict__ retr)
{
    extern __shared__ float ms[];
    for (int i = threadIdx.x; i < 16384; i += 512) ms[i] = mem[i];
    __syncthreads();
    int warp = threadIdx.x >> 5, lane = threadIdx.x & 31;
    int m0 = blockIdx.x * 64 + warp * 4;
    for (int rr = 0; rr < 4; rr++) {
        int m = m0 + rr;
        float l0 = L[(size_t)m * 64 + lane];
        float l1 = L[(size_t)m * 64 + 32 + lane];
        float mx = fmaxf(l0, l1);
        for (int o = 16; o; o >>= 1) mx = fmaxf(mx, __shfl_xor_sync(0xffffffffu, mx, o));
        float e0 = expf(l0 - mx), e1 = expf(l1 - mx);
        float s = e0 + e1;
        for (int o = 16; o; o >>= 1) s += __shfl_xor_sync(0xffffffffu, s, o);
        float inv = 1.f / s;
        e0 *= inv; e1 *= inv;
        float acc[8] = {};
        for (int j = 0; j < 32; j++) {
            float a0 = __shfl_sync(0xffffffffu, e0, j);
            float a1 = __shfl_sync(0xffffffffu, e1, j);
#pragma unroll
            for (int f = 0; f < 8; f++)
                acc[f] += a0 * ms[j * 256 + f * 32 + lane] + a1 * ms[(j + 32) * 256 + f * 32 + lane];
        }
#pragma unroll
        for (int f = 0; f < 8; f++)
            retr[(size_t)m * 256 + f * 32 + lane] = __float2half(acc[f]);
    }
}

// ---------------------------------------------------------------------------
// Launch
// ---------------------------------------------------------------------------
extern "C" void kernel_launch(void* const* d_in, const int* in_sizes, int n_in,
                              void* d_out, int out_size)
{
    const float* x        = (const float*)d_in[0];
    const float* conv1_w  = (const float*)d_in[1];
    const float* conv1_b  = (const float*)d_in[2];
    const float* bn1_g    = (const float*)d_in[3];
    const float* bn1_b    = (const float*)d_in[4];
    const float* conv2_w  = (const float*)d_in[5];
    const float* conv2_b  = (const float*)d_in[6];
    const float* bn2_g    = (const float*)d_in[7];
    const float* bn2_b    = (const float*)d_in[8];
    const float* ca_w1    = (const float*)d_in[9];
    const float* ca_w2    = (const float*)d_in[10];
    const float* sa_w     = (const float*)d_in[11];
    const float* sa_b     = (const float*)d_in[12];
    const float* memv     = (const float*)d_in[13];
    const float* mem_keys = (const float*)d_in[14];
    const float* ctrl_w1  = (const float*)d_in[15];
    const float* ctrl_b1  = (const float*)d_in[16];
    const float* ctrl_w2  = (const float*)d_in[17];
    const float* ctrl_b2  = (const float*)d_in[18];
    const float* gate_w   = (const float*)d_in[19];
    const float* gate_b   = (const float*)d_in[20];
    const float* sc_w     = (const float*)d_in[21];
    const float* sc_g     = (const float*)d_in[22];
    const float* sc_b     = (const float*)d_in[23];
    float* out = (float*)d_out;

    void* basep = nullptr;
    cudaGetSymbolAddress(&basep, g_scratch);
    float* S = (float*)basep;

    __half* xn   = (__half*)(S + OFF_XN);
    float*  t1   = S + OFF_T1;
    float*  t2   = S + OFF_T2;
    __half* xf   = (__half*)(S + OFF_XF);
    __half* retr = (__half*)(S + OFF_RETR);
    __half* t1b  = (__half*)(S + OFF_T1B);   // also h1 (half) later
    float*  scv  = S + OFF_SCV;
    float*  Lbuf = S + OFF_L;
    __half* w1r  = (__half*)(S + OFF_W1R);
    __half* w2r  = (__half*)(S + OFF_W2R);
    __half* w3r  = (__half*)(S + OFF_W3R);
    __half* wgr  = (__half*)(S + OFF_WGR);
    __half* wscr = (__half*)(S + OFF_WSCR);
    __half* KW   = (__half*)(S + OFF_KW);
    float*  kb   = S + OFF_KB;
    float*  psum = S + OFF_PSUM;
    float*  psq  = S + OFF_PSQ;
    float*  pavg = S + OFF_PAVG;
    float*  pmax = S + OFF_PMAX;
    float*  catt = S + OFF_CATT;
    float*  spm  = S + OFF_SPM;
    float*  spx  = S + OFF_SPX;
    float*  sa   = S + OFF_SA;
    float* bn1sc = S + OFF_BN1SC;  float* bn1sh = S + OFF_BN1SH;
    float* bn2sc = S + OFF_BN2SC;  float* bn2sh = S + OFF_BN2SH;
    float* scsc  = S + OFF_SCSC;   float* scsh  = S + OFF_SCSH;

    // dyn smem: stages (BN=128): 2*(16*132 + 32*66)*4 = 33792 B; F_FINAL T: 66048 B
    const int dynStage128 = 2 * (16 * 132 + 32 * 66) * 4;
    const int dynStage64  = 2 * (16 * 132 + 16 * 66) * 4;
    const int dynFinal    = 129 * 128 * 4;   // 66048
    cudaFuncSetAttribute(k_mma<128>, cudaFuncAttributeMaxDynamicSharedMemorySize, dynFinal);
    cudaFuncSetAttribute(k_mma<64>,  cudaFuncAttributeMaxDynamicSharedMemorySize, dynStage64);
    cudaFuncSetAttribute(k_softmax_retrieve, cudaFuncAttributeMaxDynamicSharedMemorySize, 65536);

    dim3 tb32x8(32, 8);
    dim3 g2(MROWS / 128, 2);   // N=256 tiles
    dim3 g1(MROWS / 128, 1);   // N=64 tiles

    // 1) x -> NHWC half
    k_nchw_to_nhwc<<<dim3(BB * 32, CIN / 32), tb32x8>>>(x, xn, CIN);

    // 2) merged weight prep + key-fold
    k_prep<<<4352, 256>>>(conv1_w, w1r, conv2_w, w2r, ctrl_w1, w3r, gate_w, wgr, sc_w, wscr);
    k_keyfold<<<MEMN, 256>>>(mem_keys, ctrl_w2, ctrl_b2, KW, kb);

    // 3) conv1: implicit im2col GEMM (+bias) -> t1 (float)
    k_mma<128><<<g2, 512, dynStage128>>>(xn, nullptr, 1 << 30, 0, 0, 7,
                                         w1r, 9 * CIN, t1, conv1_b,
                                         COUT, 9 * CIN, 1.f, F_BIAS,
                                         nullptr, nullptr, nullptr, nullptr, nullptr, nullptr);

    // 4) BN1 stats + bnrelu pass -> t1b (half)
    k_bn_partial<<<256, 256>>>(t1, psum, psq);
    k_bn_finalize<<<1, 256>>>(psum, psq, bn1_g, bn1_b, bn1sc, bn1sh);
    k_bnrelu<<<MROWS * 64 / 256, 256>>>(t1, bn1sc, bn1sh, t1b);

    // 5) conv2: implicit im2col GEMM over t1b (+bias) -> t2 (float)
    k_mma<128><<<g2, 512, dynStage128>>>(t1b, nullptr, 1 << 30, 0, 0, 8,
                                         w2r, 9 * COUT, t2, conv2_b,
                                         COUT, 9 * COUT, 1.f, F_BIAS,
                                         nullptr, nullptr, nullptr, nullptr, nullptr, nullptr);

    // 6) BN2 stats (apply fused into downstream consumers)
    k_bn_partial<<<256, 256>>>(t2, psum, psq);
    k_bn_finalize<<<1, 256>>>(psum, psq, bn2_g, bn2_b, bn2sc, bn2sh);

    // 7) channel attention (BN2 fused)
    k_ca_pool_partial<<<BB * 8, 256>>>(t2, bn2sc, bn2sh, pavg, pmax);
    k_ca_mlp<<<BB, 256>>>(pavg, pmax, ca_w1, ca_w2, catt);

    // 8) spatial attention (BN2 fused) -> xf (half)
    k_sp_pool<<<MROWS / 8, 256>>>(t2, bn2sc, bn2sh, catt, spm, spx);
    k_sa_conv<<<BB, 256>>>(spm, spx, sa_w, sa_b, sa);
    k_apply_att<<<MROWS * 64 / 256, 256>>>(t2, bn2sc, bn2sh, catt, sa, xf);

    // 9) memory module
    //   h1 = relu(xf @ ctrl_w1^T + b1) -> t1b region (half)
    k_mma<128><<<g2, 512, dynStage128>>>(xf, nullptr, 1 << 30, COUT, 0, 0,
                                         w3r, COUT, t1b, ctrl_b1,
                                         COUT, COUT, 1.f, F_BIAS | F_RELU | F_HALF,
                                         nullptr, nullptr, nullptr, nullptr, nullptr, nullptr);
    //   logits = (h1 @ KW^T)/16 + kb   -> Lbuf (float)
    k_mma<64><<<g1, 512, dynStage64>>>(t1b, nullptr, 1 << 30, COUT, 0, 0,
                                       KW, COUT, Lbuf, kb,
                                       MEMN, COUT, 1.f / 16.f, F_BIAS,
                                       nullptr, nullptr, nullptr, nullptr, nullptr, nullptr);
    k_softmax_retrieve<<<MROWS / 64, 512, 65536>>>(Lbuf, memv, retr);

    // 10) shortcut 1x1 conv -> scv (float) + BN stats
    k_mma<128><<<g2, 512, dynStage128>>>(xn, nullptr, 1 << 30, CIN, 0, 0,
                                         wscr, CIN, scv, nullptr,
                                         COUT, CIN, 1.f, 0,
                                         nullptr, nullptr, nullptr, nullptr, nullptr, nullptr);
    k_bn_partial<<<256, 256>>>(scv, psum, psq);
    k_bn_finalize<<<1, 256>>>(psum, psq, sc_g, sc_b, scsc, scsh);

    // 11) gate GEMM with fused final epilogue -> out (NCHW)
    k_mma<128><<<g2, 512, dynFinal>>>(xf, retr, COUT, COUT, COUT, 0,
                                      wgr, 2 * COUT, nullptr, gate_b,
                                      COUT, 2 * COUT, 1.f, F_BIAS | F_SIG | F_FINAL,
                                      retr, xf, scv, scsc, scsh, out);
}

// round 11
// speedup vs baseline: 1.7096x; 1.0821x over previous
#include <cuda_runtime.h>
#include <cuda_fp16.h>
#include <cstdint>
#include <cstddef>

// ---------------------------------------------------------------------------
// Problem constants
// ---------------------------------------------------------------------------
#define BB    32
#define CIN   128
#define COUT  256
#define HH    32
#define WW    32
#define HWP   1024              // H*W
#define MROWS 32768             // B*H*W
#define MEMN  64
#define EPSBN 1e-5f

// ---------------------------------------------------------------------------
// Scratch (single __device__ array; offsets in FLOAT units)
// ---------------------------------------------------------------------------
#define OFF_XN     0ull                      // half[32768*128]
#define OFF_T1     4194304ull                // float[32768*256]
#define OFF_T2     12582912ull               // float
#define OFF_XF     20971520ull               // half
#define OFF_RETR   29360128ull               // half
#define OFF_T1B    37748736ull               // half (bn1relu(t1)); also h1 half
#define OFF_SCV    46137344ull               // float
#define OFF_L      54525952ull               // float[32768*64]
#define OFF_W1R    56623104ull               // half[256*1152]
#define OFF_W2R    56918016ull               // half[256*2304]
#define OFF_W3R    57507840ull               // half[256*256]
#define OFF_WGR    57573376ull               // half[256*512]
#define OFF_WSCR   57704448ull               // half[256*128]
#define OFF_KW     57737216ull               // half[64*256]
#define OFF_KB     57753600ull               // float[64] (padded)
#define OFF_PSUM   57753856ull               // float[256*256]
#define OFF_PSQ    57819392ull
#define OFF_PMIN   57884928ull               // float[256*256]
#define OFF_PMAX   57950464ull
#define OFF_CATT   58016000ull               // 32*256
#define OFF_SPM    58024192ull               // 32768
#define OFF_SPX    58056960ull
#define OFF_SA     58089728ull
#define OFF_BN1SC  58122496ull               // 256 each
#define OFF_BN1SH  58122752ull
#define OFF_BN2SC  58123008ull
#define OFF_BN2SH  58123264ull
#define OFF_SCSC   58123520ull
#define OFF_SCSH   58123776ull
#define SCRATCH_TOTAL 58124032ull

__device__ float g_scratch[SCRATCH_TOTAL];

// ---------------------------------------------------------------------------
// fp16 MMA helper (plain sm_80+ PTX)
// ---------------------------------------------------------------------------
__device__ __forceinline__ void mma_f16(float* d, const uint32_t* a, const uint32_t* b) {
    asm volatile(
        "mma.sync.aligned.m16n8k16.row.col.f32.f16.f16.f32 "
        "{%0,%1,%2,%3}, {%4,%5,%6,%7}, {%8,%9}, {%0,%1,%2,%3};"
        : "+f"(d[0]), "+f"(d[1]), "+f"(d[2]), "+f"(d[3])
        : "r"(a[0]), "r"(a[1]), "r"(a[2]), "r"(a[3]), "r"(b[0]), "r"(b[1]));
}

// ---------------------------------------------------------------------------
// fp16 tensor-core GEMM, 256 threads, 8 warps (2m x 4n), warp tile 64x32,
// BM=128, BN template, BK=32, fragment-native smem staging.
//   C[M,N] = alpha * A[M,K] * Wt[N,K]^T  (+bias)(relu|sigmoid)(half)(stats)(final)
// F_STATS: epilogue also writes per-CTA column partials psum/psq/pmax/pmin
//          at [blockIdx.x*256 + gcol] (BN per y-block).
// F_FINAL: gate epilogue computes mo/spike/shortcut-BN/ReLU, NCHW transpose.
// ---------------------------------------------------------------------------
#define F_BIAS  1
#define F_RELU  2
#define F_SIG   8
#define F_HALF  16
#define F_FINAL 32
#define F_STATS 64

template<int BN>
__global__ void __launch_bounds__(256, 2)
k_mma(const __half* __restrict__ A, const __half* __restrict__ A2, int Ksplit,
      int lda, int lda2, int c4shift,
      const __half* __restrict__ Wt, int ldw,
      void* __restrict__ Cc, const float* __restrict__ bias,
      int N, int K, float alpha, int flags,
      const __half* __restrict__ retr, const __half* __restrict__ xfp,
      const float* __restrict__ scvp,
      const float* __restrict__ scscp, const float* __restrict__ scshp,
      float* __restrict__ outp,
      float* __restrict__ psum, float* __restrict__ psq,
      float* __restrict__ pmax, float* __restrict__ pmin)
{
    constexpr int NTW = BN / 32;              // n-tiles (8 cols) per warp
    constexpr int NB  = BN / 64;              // B uint4-load iterations
    constexpr int ASZ = 16 * 132;             // A stage words (16 tiles)
    constexpr int BSZ = (BN / 8) * 2 * 66;    // B stage words
    constexpr int STG = ASZ + BSZ;

    extern __shared__ __align__(16) uint32_t dsm[];

    const int tid  = threadIdx.x;
    const int lane = tid & 31;
    const int wid  = tid >> 5;
    const int wm   = wid & 1;                 // 2 m-warps (64 rows each)
    const int wn   = wid >> 1;                // 4 n-warps
    const int bm   = blockIdx.x * 128;
    const int bn   = blockIdx.y * BN;

    float acc[4][NTW][4];
#pragma unroll
    for (int i = 0; i < 4; i++)
#pragma unroll
        for (int j = 0; j < NTW; j++)
#pragma unroll
            for (int q = 0; q < 4; q++) acc[i][j][q] = 0.f;

    uint4 Areg[2];
    uint4 Breg[NB];

    auto loadA = [&](int k0) {
#pragma unroll
        for (int t = 0; t < 2; t++) {
            int idx = tid + t * 256;
            int r = idx >> 2, c8 = idx & 3;
            int kg = k0 + (c8 << 3);
            uint4 v = make_uint4(0u, 0u, 0u, 0u);
            if (c4shift) {
                int tap = kg >> c4shift;
                int ic  = kg & ((1 << c4shift) - 1);
                int t3  = tap / 3;
                int m   = bm + r;
                int yy  = ((m >> 5) & 31) + t3 - 1;
                int xx  = (m & 31) + (tap - t3 * 3) - 1;
                if ((unsigned)yy < 32u && (unsigned)xx < 32u)
                    v = *(const uint4*)(A +
                        (((size_t)((m >> 10) << 10) + (yy << 5) + xx) << c4shift) + ic);
            } else {
                const __half* p;
                if (kg < Ksplit) p = A  + (size_t)(bm + r) * lda  + kg;
                else             p = A2 + (size_t)(bm + r) * lda2 + (kg - Ksplit);
                v = *(const uint4*)p;
            }
            Areg[t] = v;
        }
    };

    auto loadB = [&](int k0) {
#pragma unroll
        for (int t = 0; t < NB; t++) {
            int idx = tid + t * 256;
            int r = idx >> 2, c8 = idx & 3;
            Breg[t] = *(const uint4*)(Wt + (size_t)(bn + r) * ldw + k0 + (c8 << 3));
        }
    };

    auto stsA = [&](int st) {
#pragma unroll
        for (int t = 0; t < 2; t++) {
            int idx = tid + t * 256;
            int r = idx >> 2, c8 = idx & 3;
            int mt = r >> 4, rp = r & 15, kt = c8 >> 1;
            int w  = ((c8 & 1) << 1) + (rp >> 3);
            uint32_t* tp = dsm + st * STG + (mt * 2 + kt) * 132 + (rp & 7) * 16 + w;
            tp[0]  = Areg[t].x;
            tp[4]  = Areg[t].y;
            tp[8]  = Areg[t].z;
            tp[12] = Areg[t].w;
        }
    };

    auto stsB = [&](int st) {
#pragma unroll
        for (int t = 0; t < NB; t++) {
            int idx = tid + t * 256;
            int r = idx >> 2, c8 = idx & 3;
            int nt = r >> 3, cp = r & 7, kt = c8 >> 1;
            int w  = c8 & 1;
            uint32_t* tp = dsm + st * STG + ASZ + (nt * 2 + kt) * 66 + cp * 8 + w;
            tp[0] = Breg[t].x;
            tp[2] = Breg[t].y;
            tp[4] = Breg[t].z;
            tp[6] = Breg[t].w;
        }
    };

    auto compute = [&](int st) {
        const uint32_t* sA = dsm + st * STG;
        const uint32_t* sB = sA + ASZ;
#pragma unroll
        for (int kt = 0; kt < 2; kt++) {
            uint32_t bf[NTW][2];
#pragma unroll
            for (int nt2 = 0; nt2 < NTW; nt2++)
                *(uint2*)bf[nt2] =
                    *(const uint2*)(sB + ((wn * NTW + nt2) * 2 + kt) * 66 + lane * 2);
#pragma unroll
            for (int mt2 = 0; mt2 < 4; mt2++) {
                uint32_t af[4];
                *(uint4*)af =
                    *(const uint4*)(sA + ((wm * 4 + mt2) * 2 + kt) * 132 + lane * 4);
#pragma unroll
                for (int nt2 = 0; nt2 < NTW; nt2++)
                    mma_f16(acc[mt2][nt2], af, bf[nt2]);
            }
        }
    };

    const int nIter = K >> 5;
    loadA(0); loadB(0);
    stsA(0);  stsB(0);
    if (nIter > 1) { loadA(32); loadB(32); }
    __syncthreads();
    for (int it = 0; it < nIter; ++it) {
        if (it + 1 < nIter) { stsA((it + 1) & 1); stsB((it + 1) & 1); }
        if (it + 2 < nIter) { loadA((it + 2) << 5); loadB((it + 2) << 5); }
        compute(it & 1);
        __syncthreads();
    }

    const int g = lane >> 2, t4 = lane & 3;

    if (flags & F_FINAL) {
        // fused gate->final epilogue (BN==128)
        float* T = (float*)dsm;   // 128 x 128 tile, col stride 129
#pragma unroll
        for (int mt2 = 0; mt2 < 4; mt2++) {
#pragma unroll
            for (int nt2 = 0; nt2 < NTW; nt2++) {
                int cl = wn * (NTW * 8) + nt2 * 8 + t4 * 2;
                int col = bn + cl;
                float2 bv  = *(const float2*)(bias + col);
                float2 ssc = *(const float2*)(scscp + col);
                float2 ssh = *(const float2*)(scshp + col);
#pragma unroll
                for (int h = 0; h < 2; h++) {
                    int rl = wm * 64 + mt2 * 16 + g + h * 8;
                    size_t id = (size_t)(bm + rl) * 256 + col;
                    float2 rr = __half22float2(*(const __half2*)(retr + id));
                    float2 xx = __half22float2(*(const __half2*)(xfp + id));
                    float2 sv = *(const float2*)(scvp + id);
                    float g0 = acc[mt2][nt2][h * 2 + 0] + bv.x;
                    float g1 = acc[mt2][nt2][h * 2 + 1] + bv.y;
                    g0 = 1.f / (1.f + expf(-g0));
                    g1 = 1.f / (1.f + expf(-g1));
                    float mo0 = g0 * rr.x + (1.f - g0) * xx.x;
                    float mo1 = g1 * rr.y + (1.f - g1) * xx.y;
                    float s0 = (0.1f * mo0 >= 1.f) ? 1.f : 0.f;
                    float s1 = (0.1f * mo1 >= 1.f) ? 1.f : 0.f;
                    T[(cl + 0) * 129 + rl] = fmaxf(s0 + sv.x * ssc.x + ssh.x, 0.f);
                    T[(cl + 1) * 129 + rl] = fmaxf(s1 + sv.y * ssc.y + ssh.y, 0.f);
                }
            }
        }
        __syncthreads();
        int c = tid >> 1, q = tid & 1;
        int b = bm >> 10, p0 = bm & 1023;
        float* ob = outp + ((size_t)b * 256 + bn + c) * 1024 + p0;
        const float* tr = T + c * 129;
#pragma unroll
        for (int i = 0; i < 16; i++) {
            int j4 = (q + i * 2) * 4;
            float4 w4 = make_float4(tr[j4], tr[j4 + 1], tr[j4 + 2], tr[j4 + 3]);
            *(float4*)(ob + j4) = w4;
        }
        return;
    }

    if (flags & F_STATS) {
        // store C + per-CTA column partials (sum, sumsq, max, min)
        float* sb = (float*)dsm;   // [2 wm][4 stats][BN]
#pragma unroll
        for (int nt2 = 0; nt2 < NTW; nt2++) {
            int cl  = wn * (NTW * 8) + nt2 * 8 + t4 * 2;
            int col = bn + cl;
            float2 bv = (flags & F_BIAS) ? *(const float2*)(bias + col)
                                         : make_float2(0.f, 0.f);
            float s0 = 0.f, s1 = 0.f, q0 = 0.f, q1 = 0.f;
            float mx0 = -1e30f, mx1 = -1e30f, mn0 = 1e30f, mn1 = 1e30f;
#pragma unroll
            for (int mt2 = 0; mt2 < 4; mt2++) {
#pragma unroll
                for (int h = 0; h < 2; h++) {
                    float v0 = acc[mt2][nt2][h * 2 + 0] * alpha + bv.x;
                    float v1 = acc[mt2][nt2][h * 2 + 1] * alpha + bv.y;
                    int row = bm + wm * 64 + mt2 * 16 + g + h * 8;
                    *(float2*)((float*)Cc + (size_t)row * N + col) = make_float2(v0, v1);
                    s0 += v0; q0 += v0 * v0; mx0 = fmaxf(mx0, v0); mn0 = fminf(mn0, v0);
                    s1 += v1; q1 += v1 * v1; mx1 = fmaxf(mx1, v1); mn1 = fminf(mn1, v1);
                }
            }
#pragma unroll
            for (int o = 4; o <= 16; o <<= 1) {
                s0 += __shfl_xor_sync(0xffffffffu, s0, o);
                s1 += __shfl_xor_sync(0xffffffffu, s1, o);
                q0 += __shfl_xor_sync(0xffffffffu, q0, o);
                q1 += __shfl_xor_sync(0xffffffffu, q1, o);
                mx0 = fmaxf(mx0, __shfl_xor_sync(0xffffffffu, mx0, o));
                mx1 = fmaxf(mx1, __shfl_xor_sync(0xffffffffu, mx1, o));
                mn0 = fminf(mn0, __shfl_xor_sync(0xffffffffu, mn0, o));
                mn1 = fminf(mn1, __shfl_xor_sync(0xffffffffu, mn1, o));
            }
            if (g == 0) {
                sb[(wm * 4 + 0) * BN + cl] = s0;  sb[(wm * 4 + 0) * BN + cl + 1] = s1;
                sb[(wm * 4 + 1) * BN + cl] = q0;  sb[(wm * 4 + 1) * BN + cl + 1] = q1;
                sb[(wm * 4 + 2) * BN + cl] = mx0; sb[(wm * 4 + 2) * BN + cl + 1] = mx1;
                sb[(wm * 4 + 3) * BN + cl] = mn0; sb[(wm * 4 + 3) * BN + cl + 1] = mn1;
            }
        }
        __syncthreads();
        if (tid < BN) {
            int o = blockIdx.x * 256 + bn + tid;
            psum[o] = sb[0 * BN + tid] + sb[4 * BN + tid];
            psq [o] = sb[1 * BN + tid] + sb[5 * BN + tid];
            pmax[o] = fmaxf(sb[2 * BN + tid], sb[6 * BN + tid]);
            pmin[o] = fminf(sb[3 * BN + tid], sb[7 * BN + tid]);
        }
        return;
    }

    // normal epilogue
#pragma unroll
    for (int mt2 = 0; mt2 < 4; mt2++) {
#pragma unroll
        for (int nt2 = 0; nt2 < NTW; nt2++) {
            int row0 = bm + wm * 64 + mt2 * 16 + g;
            int col  = bn + wn * (NTW * 8) + nt2 * 8 + t4 * 2;
            float2 bv = (flags & F_BIAS) ? *(const float2*)(bias + col)
                                         : make_float2(0.f, 0.f);
#pragma unroll
            for (int h = 0; h < 2; h++) {
                float v0 = acc[mt2][nt2][h * 2 + 0] * alpha + bv.x;
                float v1 = acc[mt2][nt2][h * 2 + 1] * alpha + bv.y;
                if (flags & F_RELU) { v0 = fmaxf(v0, 0.f); v1 = fmaxf(v1, 0.f); }
                if (flags & F_SIG) {
                    v0 = 1.f / (1.f + expf(-v0));
                    v1 = 1.f / (1.f + expf(-v1));
                }
                size_t id = (size_t)(row0 + h * 8) * N + col;
                if (flags & F_HALF)
                    *(__half2*)((__half*)Cc + id) = __floats2half2_rn(v0, v1);
                else
                    *(float2*)((float*)Cc + id) = make_float2(v0, v1);
            }
        }
    }
}

// ---------------------------------------------------------------------------
// NCHW -> NHWC transpose (x, C=128), output half
// ---------------------------------------------------------------------------
__global__ void k_nchw_to_nhwc(const float* __restrict__ src, __half* __restrict__ dst, int C)
{
    __shared__ float tile[32][33];
    int b  = blockIdx.x >> 5;
    int p0 = (blockIdx.x & 31) << 5;
    int c0 = blockIdx.y << 5;
    for (int i = threadIdx.y; i < 32; i += 8)
        tile[i][threadIdx.x] = src[((size_t)b * C + c0 + i) * HWP + p0 + threadIdx.x];
    __syncthreads();
    for (int i = threadIdx.y; i < 32; i += 8)
        dst[((size_t)(b << 10) + p0 + i) * C + c0 + threadIdx.x] =
            __float2half(tile[threadIdx.x][i]);
}

// ---------------------------------------------------------------------------
// Merged weight prep
// ---------------------------------------------------------------------------
__global__ void k_prep(const float* __restrict__ w1, __half* __restrict__ w1r,
                       const float* __restrict__ w2, __half* __restrict__ w2r,
                       const float* __restrict__ c1, __half* __restrict__ c1r,
                       const float* __restrict__ gw, __half* __restrict__ gwr,
                       const float* __restrict__ sw, __half* __restrict__ swr)
{
    const int n1 = COUT * CIN * 9;        // 294912
    const int n2 = COUT * COUT * 9;       // 589824
    const int n3 = COUT * COUT;           // 65536
    const int n4 = COUT * 2 * COUT;       // 131072
    int idx = blockIdx.x * 256 + threadIdx.x;
    if (idx < n1) {
        int n = idx / (CIN * 9), rem = idx - n * (CIN * 9);
        int ic = rem / 9, tap = rem - ic * 9;
        w1r[(size_t)n * CIN * 9 + tap * CIN + ic] = __float2half(w1[idx]);
        return;
    }
    idx -= n1;
    if (idx < n2) {
        int n = idx / (COUT * 9), rem = idx - n * (COUT * 9);
        int ic = rem / 9, tap = rem - ic * 9;
        w2r[(size_t)n * COUT * 9 + tap * COUT + ic] = __float2half(w2[idx]);
        return;
    }
    idx -= n2;
    if (idx < n3) { c1r[idx] = __float2half(c1[idx]); return; }
    idx -= n3;
    if (idx < n4) { gwr[idx] = __float2half(gw[idx]); return; }
    idx -= n4;
    if (idx < COUT * CIN) swr[idx] = __float2half(sw[idx]);
}

// ---------------------------------------------------------------------------
// Fold mem_keys into ctrl_w2
// ---------------------------------------------------------------------------
__global__ void k_keyfold(const float* __restrict__ keys, const float* __restrict__ W2,
                          const float* __restrict__ b2,
                          __half* __restrict__ KW, float* __restrict__ kb)
{
    __shared__ float krow[256];
    __shared__ float red[256];
    int j = blockIdx.x, t = threadIdx.x;
    krow[t] = keys[j * 256 + t];
    __syncthreads();
    float acc = 0.f;
    for (int c = 0; c < 256; c++) acc += krow[c] * W2[c * 256 + t];
    KW[j * 256 + t] = __float2half(acc);
    red[t] = krow[t] * b2[t];
    __syncthreads();
    for (int o = 128; o; o >>= 1) { if (t < o) red[t] += red[t + o]; __syncthreads(); }
    if (t == 0) kb[j] = red[0] * (1.f / 16.f);
}

// ---------------------------------------------------------------------------
// BN finalize (partials produced by GEMM F_STATS epilogues)
// ---------------------------------------------------------------------------
__global__ void k_bn_finalize(const float* __restrict__ psum, const float* __restrict__ psq,
                              const float* __restrict__ gamma, const float* __restrict__ beta,
                              float* __restrict__ scale, float* __restrict__ shift)
{
    int c = threadIdx.x;
    float s = 0.f, s2 = 0.f;
    for (int i = 0; i < 256; i++) { s += psum[i * 256 + c]; s2 += psq[i * 256 + c]; }
    float mean = s / 32768.f;
    float var  = s2 / 32768.f - mean * mean;
    float sc   = gamma[c] * rsqrtf(var + EPSBN);
    scale[c] = sc;
    shift[c] = beta[c] - mean * sc;
}

// t1b = half(relu(t1*sc + sh))
__global__ void k_bnrelu(const float* __restrict__ t, const float* __restrict__ scale,
                         const float* __restrict__ shift, __half* __restrict__ o)
{
    int idx = blockIdx.x * 256 + threadIdx.x;   // MROWS*64 float4s
    int c4 = idx & 63;
    float4 v  = ((const float4*)t)[idx];
    float4 sc = ((const float4*)scale)[c4];
    float4 sh = ((const float4*)shift)[c4];
    float a0 = fmaxf(v.x * sc.x + sh.x, 0.f);
    float a1 = fmaxf(v.y * sc.y + sh.y, 0.f);
    float a2 = fmaxf(v.z * sc.z + sh.z, 0.f);
    float a3 = fmaxf(v.w * sc.w + sh.w, 0.f);
    __half2* op = (__half2*)(o + (size_t)idx * 4);
    op[0] = __floats2half2_rn(a0, a1);
    op[1] = __floats2half2_rn(a2, a3);
}

// ---------------------------------------------------------------------------
// Channel attention MLP — pooled stats derived from conv2 F_STATS partials.
// avg_bn = sc*(rawsum/1024)+sh ; max_bn = sc>=0 ? sc*rawmax+sh : sc*rawmin+sh
// ---------------------------------------------------------------------------
__global__ void k_ca_mlp(const float* __restrict__ psum, const float* __restrict__ pmax,
                         const float* __restrict__ pmin,
                         const float* __restrict__ bsc, const float* __restrict__ bsh,
                         const float* __restrict__ w1, const float* __restrict__ w2,
                         float* __restrict__ catt)
{
    __shared__ float av[256], mx[256], h[32];
    int b = blockIdx.x, c = threadIdx.x;
    float s = 0.f, m = -1e30f, mn = 1e30f;
    for (int i = 0; i < 8; i++) {
        int o = (b * 8 + i) * 256 + c;
        s += psum[o];
        m  = fmaxf(m,  pmax[o]);
        mn = fminf(mn, pmin[o]);
    }
    float sc = bsc[c], sh = bsh[c];
    av[c] = sc * (s / 1024.f) + sh;
    mx[c] = (sc >= 0.f) ? (sc * m + sh) : (sc * mn + sh);
    __syncthreads();
    if (c < 32) {
        const float* src = (c < 16) ? av : mx;
        int j = c & 15;
        float acc = 0.f;
        for (int k = 0; k < 256; k++) acc += w1[j * 256 + k] * src[k];
        h[c] = fmaxf(acc, 0.f);
    }
    __syncthreads();
    float acc = 0.f;
#pragma unroll
    for (int j = 0; j < 16; j++) acc += w2[c * 16 + j] * (h[j] + h[16 + j]);
    catt[b * 256 + c] = 1.f / (1.f + expf(-acc));
}

// ---------------------------------------------------------------------------
// Spatial attention (BN2 fused)
// ---------------------------------------------------------------------------
__global__ void k_sp_pool(const float* __restrict__ t2,
                          const float* __restrict__ bsc, const float* __restrict__ bsh,
                          const float* __restrict__ catt,
                          float* __restrict__ spm, float* __restrict__ spx)
{
    int warp = threadIdx.x >> 5, lane = threadIdx.x & 31;
    int m = blockIdx.x * 8 + warp;
    int b = m >> 10;
    float s = 0.f, mx = -1e30f;
#pragma unroll
    for (int i = 0; i < 8; i++) {
        int c = i * 32 + lane;
        float v = (t2[(size_t)m * 256 + c] * bsc[c] + bsh[c]) * catt[b * 256 + c];
        s += v; mx = fmaxf(mx, v);
    }
    for (int o = 16; o; o >>= 1) {
        s += __shfl_xor_sync(0xffffffffu, s, o);
        mx = fmaxf(mx, __shfl_xor_sync(0xffffffffu, mx, o));
    }
    if (lane == 0) { spm[m] = s / 256.f; spx[m] = mx; }
}

__global__ void k_sa_conv(const float* __restrict__ spm, const float* __restrict__ spx,
                          const float* __restrict__ saw, const float* __restrict__ sab,
                          float* __restrict__ sa)
{
    __shared__ float sm[1024], sx[1024], w[98];
    int b = blockIdx.x, t = threadIdx.x;
    for (int i = t; i < 1024; i += 256) { sm[i] = spm[b * 1024 + i]; sx[i] = spx[b * 1024 + i]; }
    if (t < 98) w[t] = saw[t];
    __syncthreads();
    float bias = sab[0];
    for (int i = t; i < 1024; i += 256) {
        int y = i >> 5, x = i & 31;
        float acc = bias;
#pragma unroll
        for (int ky = 0; ky < 7; ky++) {
            int yy = y + ky - 3; if ((unsigned)yy >= 32u) continue;
#pragma unroll
            for (int kx = 0; kx < 7; kx++) {
                int xx = x + kx - 3; if ((unsigned)xx >= 32u) continue;
                acc += w[ky * 7 + kx] * sm[yy * 32 + xx] + w[49 + ky * 7 + kx] * sx[yy * 32 + xx];
            }
        }
        sa[b * 1024 + i] = 1.f / (1.f + expf(-acc));
    }
}

// xf = half( (t2*bsc+bsh) * catt * sa )
__global__ void k_apply_att(const float* __restrict__ t2,
                            const float* __restrict__ bsc, const float* __restrict__ bsh,
                            const float* __restrict__ catt,
                            const float* __restrict__ sa, __half* __restrict__ xf)
{
    int idx = blockIdx.x * 256 + threadIdx.x;
    int m = idx >> 6, c4 = idx & 63;
    int b = m >> 10;
    float s = sa[m];
    float4 v  = ((const float4*)t2)[idx];
    float4 sc = ((const float4*)bsc)[c4];
    float4 sh = ((const float4*)bsh)[c4];
    float4 ca = ((const float4*)(catt + b * 256))[c4];
    float a0 = (v.x * sc.x + sh.x) * ca.x * s;
    float a1 = (v.y * sc.y + sh.y) * ca.y * s;
    float a2 = (v.z * sc.z + sh.z) * ca.z * s;
    float a3 = (v.w * sc.w + sh.w) * ca.w * s;
    __half2* op = (__half2*)(xf + (size_t)idx * 4);
    op[0] = __floats2half2_rn(a0, a1);
    op[1] = __floats2half2_rn(a2, a3);
}

// ---------------------------------------------------------------------------
// Fused softmax over 64 logits + retrieved = attn @ mem (half out).
// ---------------------------------------------------------------------------
__global__ void __launch_bounds__(512)
k_softmax_retrieve(const float* __restrict__ L, const float* __restrict__ mem,
                   __half* __restrict__ retr)
{
    extern __shared__ float ms[];
    for (int i = threadIdx.x; i < 16384; i += 512) ms[i] = mem[i];
    __syncthreads();
    int warp = threadIdx.x >> 5, lane = threadIdx.x & 31;
    int m0 = blockIdx.x * 64 + warp * 4;
    for (int rr = 0; rr < 4; rr++) {
        int m = m0 + rr;
        float l0 = L[(size_t)m * 64 + lane];
        float l1 = L[(size_t)m * 64 + 32 + lane];
        float mx = fmaxf(l0, l1);
        for (int o = 16; o; o >>= 1) mx = fmaxf(mx, __shfl_xor_sync(0xffffffffu, mx, o));
        float e0 = expf(l0 - mx), e1 = expf(l1 - mx);
        float s = e0 + e1;
        for (int o = 16; o; o >>= 1) s += __shfl_xor_sync(0xffffffffu, s, o);
        float inv = 1.f / s;
        e0 *= inv; e1 *= inv;
        float acc[8] = {};
        for (int j = 0; j < 32; j++) {
            float a0 = __shfl_sync(0xffffffffu, e0, j);
            float a1 = __shfl_sync(0xffffffffu, e1, j);
#pragma unroll
            for (int f = 0; f < 8; f++)
                acc[f] += a0 * ms[j * 256 + f * 32 + lane] + a1 * ms[(j + 32) * 256 + f * 32 + lane];
        }
#pragma unroll
        for (int f = 0; f < 8; f++)
            retr[(size_t)m * 256 + f * 32 + lane] = __float2half(acc[f]);
    }
}

// ---------------------------------------------------------------------------
// Launch
// ---------------------------------------------------------------------------
extern "C" void kernel_launch(void* const* d_in, const int* in_sizes, int n_in,
                              void* d_out, int out_size)
{
    const float* x        = (const float*)d_in[0];
    const float* conv1_w  = (const float*)d_in[1];
    const float* conv1_b  = (const float*)d_in[2];
    const float* bn1_g    = (const float*)d_in[3];
    const float* bn1_b    = (const float*)d_in[4];
    const float* conv2_w  = (const float*)d_in[5];
    const float* conv2_b  = (const float*)d_in[6];
    const float* bn2_g    = (const float*)d_in[7];
    const float* bn2_b    = (const float*)d_in[8];
    const float* ca_w1    = (const float*)d_in[9];
    const float* ca_w2    = (const float*)d_in[10];
    const float* sa_w     = (const float*)d_in[11];
    const float* sa_b     = (const float*)d_in[12];
    const float* memv     = (const float*)d_in[13];
    const float* mem_keys = (const float*)d_in[14];
    const float* ctrl_w1  = (const float*)d_in[15];
    const float* ctrl_b1  = (const float*)d_in[16];
    const float* ctrl_w2  = (const float*)d_in[17];
    const float* ctrl_b2  = (const float*)d_in[18];
    const float* gate_w   = (const float*)d_in[19];
    const float* gate_b   = (const float*)d_in[20];
    const float* sc_w     = (const float*)d_in[21];
    const float* sc_g     = (const float*)d_in[22];
    const float* sc_b     = (const float*)d_in[23];
    float* out = (float*)d_out;

    void* basep = nullptr;
    cudaGetSymbolAddress(&basep, g_scratch);
    float* S = (float*)basep;

    __half* xn   = (__half*)(S + OFF_XN);
    float*  t1   = S + OFF_T1;
    float*  t2   = S + OFF_T2;
    __half* xf   = (__half*)(S + OFF_XF);
    __half* retr = (__half*)(S + OFF_RETR);
    __half* t1b  = (__half*)(S + OFF_T1B);
    float*  scv  = S + OFF_SCV;
    float*  Lbuf = S + OFF_L;
    __half* w1r  = (__half*)(S + OFF_W1R);
    __half* w2r  = (__half*)(S + OFF_W2R);
    __half* w3r  = (__half*)(S + OFF_W3R);
    __half* wgr  = (__half*)(S + OFF_WGR);
    __half* wscr = (__half*)(S + OFF_WSCR);
    __half* KW   = (__half*)(S + OFF_KW);
    float*  kb   = S + OFF_KB;
    float*  psum = S + OFF_PSUM;
    float*  psq  = S + OFF_PSQ;
    float*  pmin = S + OFF_PMIN;
    float*  pmax = S + OFF_PMAX;
    float*  catt = S + OFF_CATT;
    float*  spm  = S + OFF_SPM;
    float*  spx  = S + OFF_SPX;
    float*  sa   = S + OFF_SA;
    float* bn1sc = S + OFF_BN1SC;  float* bn1sh = S + OFF_BN1SH;
    float* bn2sc = S + OFF_BN2SC;  float* bn2sh = S + OFF_BN2SH;
    float* scsc  = S + OFF_SCSC;   float* scsh  = S + OFF_SCSH;

    // dyn smem: stage (BN=128) = 2*(16*132 + 32*66)*4 = 33792 B ; F_FINAL = 66048 B
    const int dynStage128 = 2 * (16 * 132 + 32 * 66) * 4;
    const int dynStage64  = 2 * (16 * 132 + 16 * 66) * 4;
    const int dynFinal    = 129 * 128 * 4;
    cudaFuncSetAttribute(k_mma<128>, cudaFuncAttributeMaxDynamicSharedMemorySize, dynFinal);
    cudaFuncSetAttribute(k_mma<64>,  cudaFuncAttributeMaxDynamicSharedMemorySize, dynStage64);
    cudaFuncSetAttribute(k_softmax_retrieve, cudaFuncAttributeMaxDynamicSharedMemorySize, 65536);

    dim3 tb32x8(32, 8);
    dim3 g2(MROWS / 128, 2);   // N=256
    dim3 g1(MROWS / 128, 1);   // N=64

    // 1) x -> NHWC half
    k_nchw_to_nhwc<<<dim3(BB * 32, CIN / 32), tb32x8>>>(x, xn, CIN);

    // 2) weight prep + key-fold
    k_prep<<<4352, 256>>>(conv1_w, w1r, conv2_w, w2r, ctrl_w1, w3r, gate_w, wgr, sc_w, wscr);
    k_keyfold<<<MEMN, 256>>>(mem_keys, ctrl_w2, ctrl_b2, KW, kb);

    // 3) conv1 (+bias, stats) -> t1
    k_mma<128><<<g2, 256, dynStage128>>>(xn, nullptr, 1 << 30, 0, 0, 7,
                                         w1r, 9 * CIN, t1, conv1_b,
                                         COUT, 9 * CIN, 1.f, F_BIAS | F_STATS,
                                         nullptr, nullptr, nullptr, nullptr, nullptr, nullptr,
                                         psum, psq, pmax, pmin);
    k_bn_finalize<<<1, 256>>>(psum, psq, bn1_g, bn1_b, bn1sc, bn1sh);
    k_bnrelu<<<MROWS * 64 / 256, 256>>>(t1, bn1sc, bn1sh, t1b);

    // 4) conv2 (+bias, stats) -> t2
    k_mma<128><<<g2, 256, dynStage128>>>(t1b, nullptr, 1 << 30, 0, 0, 8,
                                         w2r, 9 * COUT, t2, conv2_b,
                                         COUT, 9 * COUT, 1.f, F_BIAS | F_STATS,
                                         nullptr, nullptr, nullptr, nullptr, nullptr, nullptr,
                                         psum, psq, pmax, pmin);
    k_bn_finalize<<<1, 256>>>(psum, psq, bn2_g, bn2_b, bn2sc, bn2sh);

    // 5) channel attention from conv2 partials
    k_ca_mlp<<<BB, 256>>>(psum, pmax, pmin, bn2sc, bn2sh, ca_w1, ca_w2, catt);

    // 6) spatial attention (BN2 fused) -> xf (half)
    k_sp_pool<<<MROWS / 8, 256>>>(t2, bn2sc, bn2sh, catt, spm, spx);
    k_sa_conv<<<BB, 256>>>(spm, spx, sa_w, sa_b, sa);
    k_apply_att<<<MROWS * 64 / 256, 256>>>(t2, bn2sc, bn2sh, catt, sa, xf);

    // 7) memory module
    k_mma<128><<<g2, 256, dynStage128>>>(xf, nullptr, 1 << 30, COUT, 0, 0,
                                         w3r, COUT, t1b, ctrl_b1,
                                         COUT, COUT, 1.f, F_BIAS | F_RELU | F_HALF,
                                         nullptr, nullptr, nullptr, nullptr, nullptr, nullptr,
                                         nullptr, nullptr, nullptr, nullptr);
    k_mma<64><<<g1, 256, dynStage64>>>(t1b, nullptr, 1 << 30, COUT, 0, 0,
                                       KW, COUT, Lbuf, kb,
                                       MEMN, COUT, 1.f / 16.f, F_BIAS,
                                       nullptr, nullptr, nullptr, nullptr, nullptr, nullptr,
                                       nullptr, nullptr, nullptr, nullptr);
    k_softmax_retrieve<<<MROWS / 64, 512, 65536>>>(Lbuf, memv, retr);

    // 8) shortcut 1x1 conv (stats) -> scv
    k_mma<128><<<g2, 256, dynStage128>>>(xn, nullptr, 1 << 30, CIN, 0, 0,
                                         wscr, CIN, scv, nullptr,
                                         COUT, CIN, 1.f, F_STATS,
                                         nullptr, nullptr, nullptr, nullptr, nullptr, nullptr,
                                         psum, psq, pmax, pmin);
    k_bn_finalize<<<1, 256>>>(psum, psq, sc_g, sc_b, scsc, scsh);

    // 9) gate GEMM with fused final epilogue -> out (NCHW)
    k_mma<128><<<g2, 256, dynFinal>>>(xf, retr, COUT, COUT, COUT, 0,
                                      wgr, 2 * COUT, nullptr, gate_b,
                                      COUT, 2 * COUT, 1.f, F_BIAS | F_SIG | F_FINAL,
                                      retr, xf, scv, scsc, scsh, out,
                                      nullptr, nullptr, nullptr, nullptr);
}